// round 12
// baseline (speedup 1.0000x reference)
#include <cuda_runtime.h>
#include <math.h>

#define NQ       16
#define BATCH    256
#define NL       4
#define DIN      512
#define OUTD     10

typedef unsigned long long ull;

// ---------------- scratch (SoA state, packed across amp bit 0 = qubit 15) ----------------
__device__ __align__(16) ull g_re[BATCH * 32768];        // 64 MB re pairs
__device__ __align__(16) ull g_im[BATCH * 32768];        // 64 MB im pairs
__device__ ull   g_T0u[BATCH * 128];
__device__ float g_T1[BATCH * 256];
__device__ ull   g_Rnd[NL * 9 * 12];         // round gates: [l][ubit 0..8] -> qubit 14-ubit
__device__ ull   g_OwnCk[NL * 3 * 12];       // own chunk gates: [pi][kbit]
__device__ ull   g_Def[NL * 3 * 12];         // deferred gates: [slot=layer][kbit]
__device__ ull   g_Lane[NL * 6];             // lane (q15) gate consts
__device__ __align__(16) ull g_EpRe[3 * 4096], g_EpIm[3 * 4096], g_EpImN[3 * 4096];
__device__ ull   g_DjBRe[2*16], g_DjBIm[2*16], g_DjBImN[2*16];  // [l/2][s3][k] layers 0,2
__device__ ull   g_DjARe[32],  g_DjAIm[32],  g_DjAImN[32];      // [k][q2b][t8] layer 1
__device__ float g_zpart[BATCH * 8 * 16];

// ---------------- f32x2 helpers ----------------
__device__ __forceinline__ ull pk2(float lo, float hi) {
    ull r; asm("mov.b64 %0, {%1, %2};" : "=l"(r) : "f"(lo), "f"(hi)); return r;
}
__device__ __forceinline__ ull bc2(float v) {
    ull r; asm("mov.b64 %0, {%1, %1};" : "=l"(r) : "f"(v)); return r;
}
__device__ __forceinline__ void up2(ull v, float& lo, float& hi) {
    asm("mov.b64 {%0, %1}, %2;" : "=f"(lo), "=f"(hi) : "l"(v));
}
__device__ __forceinline__ ull f2fma(ull a, ull b, ull c) {
    ull d; asm("fma.rn.f32x2 %0, %1, %2, %3;" : "=l"(d) : "l"(a), "l"(b), "l"(c)); return d;
}
__device__ __forceinline__ ull f2mul(ull a, ull b) {
    ull d; asm("mul.rn.f32x2 %0, %1, %2;" : "=l"(d) : "l"(a), "l"(b)); return d;
}
__device__ __forceinline__ ull swap2(ull v) {
    float lo, hi; up2(v, lo, hi); return pk2(hi, lo);
}
__device__ __forceinline__ int swz(int i) { return i ^ ((i >> 3) & 15); }

// ---------------- prep ----------------
__global__ void prep_kernel(const float* __restrict__ x,
                            const float* __restrict__ W_enc,
                            const float* __restrict__ b_enc,
                            const float* __restrict__ theta)
{
    __shared__ float partial[256];
    __shared__ float cs[NQ], ss[NQ];
    __shared__ float2 Ush[NL * NQ * 4];

    int b   = blockIdx.x;
    int tid = threadIdx.x;
    int q   = tid & 15;
    int seg = tid >> 4;

    {
        float acc = 0.f;
        const float* xb = x + b * DIN;
        int d0 = seg * 32;
        #pragma unroll 8
        for (int d = d0; d < d0 + 32; d++)
            acc += xb[d] * W_enc[d * NQ + q];
        partial[tid] = acc;
    }
    __syncthreads();
    if (tid < NQ) {
        float s = b_enc[tid];
        #pragma unroll
        for (int g = 0; g < 16; g++) s += partial[g * 16 + tid];
        float ang = tanhf(s) * 3.14159265358979323846f;
        cs[tid] = cosf(0.5f * ang);
        ss[tid] = sinf(0.5f * ang);
    }
    __syncthreads();

    // product tables over amplitude bits (amp bit k -> qubit 15-k)
    {
        int m = tid;
        float p0 = 1.f, p1 = 1.f;
        #pragma unroll
        for (int k = 0; k < 8; k++) {
            int bit = (m >> k) & 1;
            p0 *= bit ? ss[15 - k] : cs[15 - k];
            p1 *= bit ? ss[7 - k]  : cs[7 - k];
        }
        ((float*)g_T0u)[b * 256 + m] = p0;
        g_T1[b * 256 + m] = p1;
    }

    if (b == 0) {
        if (tid < NL * NQ) {
            int l = tid >> 4, qq = tid & 15;
            const float* th = theta + (l * NQ + qq) * 3;
            float a0 = th[0], a1 = th[1], a2 = th[2];
            float ca = cosf(0.5f * a0), sa = sinf(0.5f * a0);
            float cb = cosf(0.5f * a1), sb = sinf(0.5f * a1);
            float cz = cosf(0.5f * a2), sz = sinf(0.5f * a2);
            float2 em = make_float2(cz, -sz);
            float2 ep = make_float2(cz,  sz);
            float2 r00 = make_float2( cb * em.x,  cb * em.y);
            float2 r01 = make_float2(-sb * ep.x, -sb * ep.y);
            float2 r10 = make_float2( sb * em.x,  sb * em.y);
            float2 r11 = make_float2( cb * ep.x,  cb * ep.y);
            float2 u00 = make_float2(ca * r00.x + sa * r10.y, ca * r00.y - sa * r10.x);
            float2 u01 = make_float2(ca * r01.x + sa * r11.y, ca * r01.y - sa * r11.x);
            float2 u10 = make_float2(sa * r00.y + ca * r10.x, -sa * r00.x + ca * r10.y);
            float2 u11 = make_float2(sa * r01.y + ca * r11.x, -sa * r01.x + ca * r11.y);
            int base = tid * 4;
            Ush[base + 0] = u00; Ush[base + 1] = u01;
            Ush[base + 2] = u10; Ush[base + 3] = u11;
        }
        __syncthreads();

        // round gates: [l][ubit][12], ubit 0..8 -> qubit 14-ubit
        for (int k = tid; k < NL * 108; k += 256) {
            int l = k / 108, rem = k % 108, ub = rem / 12, e = rem % 12;
            int j2 = e / 3, kind = e % 3;
            float2 u = Ush[(l * 16 + (14 - ub)) * 4 + j2];
            float v = (kind == 0) ? u.x : ((kind == 1) ? u.y : -u.y);
            g_Rnd[k] = bc2(v);
        }
        // own chunk gates: [pi][kbit][12]; covA(pi even): q = 5-kbit; covB: q = 2-kbit
        for (int k = tid; k < NL * 36; k += 256) {
            int pi = k / 36, rem = k % 36, kb = rem / 12, e = rem % 12;
            int qq = ((pi & 1) ? 2 : 5) - kb;
            int j2 = e / 3, kind = e % 3;
            float2 u = Ush[(pi * 16 + qq) * 4 + j2];
            float v = (kind == 0) ? u.x : ((kind == 1) ? u.y : -u.y);
            g_OwnCk[k] = bc2(v);
        }
        // deferred gates: [slot=s][kbit][12]; s even: q = 2-kbit; s odd: q = 5-kbit
        for (int k = tid; k < NL * 36; k += 256) {
            int s = k / 36, rem = k % 36, kb = rem / 12, e = rem % 12;
            int qq = ((s & 1) ? 5 : 2) - kb;
            int j2 = e / 3, kind = e % 3;
            float2 u = Ush[(s * 16 + qq) * 4 + j2];
            float v = (kind == 0) ? u.x : ((kind == 1) ? u.y : -u.y);
            g_Def[k] = bc2(v);
        }
        // lane gate (qubit 15)
        if (tid < NL) {
            int l = tid;
            float2 u00 = Ush[(l * 16 + 15) * 4 + 0];
            float2 u01 = Ush[(l * 16 + 15) * 4 + 1];
            float2 u10 = Ush[(l * 16 + 15) * 4 + 2];
            float2 u11 = Ush[(l * 16 + 15) * 4 + 3];
            g_Lane[l * 6 + 0] = pk2(u00.x, u11.x);
            g_Lane[l * 6 + 1] = pk2(u01.x, u10.x);
            g_Lane[l * 6 + 2] = pk2(-u00.y, -u11.y);
            g_Lane[l * 6 + 3] = pk2(-u01.y, -u10.y);
            g_Lane[l * 6 + 4] = pk2(u00.y, u11.y);
            g_Lane[l * 6 + 5] = pk2(u01.y, u10.y);
        }
    }
}

// ---------------- Ep tables: per-pass epilogue diagonal (passes 0,1,2) ----------------
__global__ void ep_kernel(const float* __restrict__ phi)
{
    int gid = blockIdx.x * 1024 + threadIdx.x;   // 3*4096
    int pi = gid >> 12, u = gid & 4095;
    float ang = 0.f, lp;
    if (pi == 1) {
        // layer 1, covB: edges (6,7)..(13,14) over u bits 0..8; (0,1),(1,2) over k bits;
        // lane: (14,15) + (15,0)
        #pragma unroll
        for (int bb = 0; bb < 8; bb++) {
            float sA = 1.f - 2.f * ((u >> (bb + 1)) & 1);
            float sB = 1.f - 2.f * ((u >> bb) & 1);
            ang += __ldg(&phi[16 + 13 - bb]) * sA * sB;
        }
        float sq0 = 1.f - 2.f * ((u >> 11) & 1);
        float sq1 = 1.f - 2.f * ((u >> 10) & 1);
        float sq2 = 1.f - 2.f * ((u >> 9) & 1);
        ang += __ldg(&phi[16 + 0]) * sq0 * sq1 + __ldg(&phi[16 + 1]) * sq1 * sq2;
        lp = __ldg(&phi[16 + 14]) * (1.f - 2.f * (u & 1)) + __ldg(&phi[16 + 15]) * sq0;
    } else {
        // covA passes: layer l = pi (0 or 2): edges (3,4)..(13,14) + lane edge (14,15)
        int l = pi;
        #pragma unroll
        for (int bb = 0; bb < 11; bb++) {
            float sA = 1.f - 2.f * ((u >> (bb + 1)) & 1);
            float sB = 1.f - 2.f * ((u >> bb) & 1);
            ang += __ldg(&phi[l * 16 + 13 - bb]) * sA * sB;
        }
        lp = __ldg(&phi[l * 16 + 14]) * (1.f - 2.f * (u & 1));
    }
    float a0 = ang + lp, a1 = ang - lp;
    float c0, s0, c1, s1;
    sincosf(0.5f * a0, &s0, &c0);
    sincosf(0.5f * a1, &s1, &c1);
    g_EpRe[gid]  = pk2(c0, c1);
    g_EpIm[gid]  = pk2(-s0, -s1);
    g_EpImN[gid] = pk2(s0, s1);
}

// ---------------- Dj tables: chunk-applied deferred diagonals ----------------
__global__ void dj_kernel(const float* __restrict__ phi)
{
    int tid = threadIdx.x;   // 64
    if (tid < 32) {
        // DjB[lh][s3][k]: edges (0,1),(1,2),(2,3),(15,0); lh=0 -> layer0, lh=1 -> layer2
        int i = tid;
        int lh = i >> 4, l = lh * 2, s3i = (i >> 3) & 1, k = i & 7;
        float s0v = 1.f - 2.f * ((k >> 2) & 1);
        float s1v = 1.f - 2.f * ((k >> 1) & 1);
        float s2v = 1.f - 2.f * (k & 1);
        float s3v = 1.f - 2.f * (float)s3i;
        const float* ph = phi + l * 16;
        float ang = __ldg(&ph[0]) * s0v * s1v + __ldg(&ph[1]) * s1v * s2v + __ldg(&ph[2]) * s2v * s3v;
        float C = __ldg(&ph[15]) * s0v;
        float a0 = ang + C, a1 = ang - C;
        float c0, s0, c1, s1;
        sincosf(0.5f * a0, &s0, &c0);
        sincosf(0.5f * a1, &s1, &c1);
        g_DjBRe[i]  = pk2(c0, c1);
        g_DjBIm[i]  = pk2(-s0, -s1);
        g_DjBImN[i] = pk2(s0, s1);
    } else {
        // DjA[k][q2b][t8]: edges (2,3),(3,4),(4,5),(5,6); layer 1
        int i = tid - 32;
        int k = i >> 2, q2b = (i >> 1) & 1, t8 = i & 1;
        float s3v = 1.f - 2.f * ((k >> 2) & 1);
        float s4v = 1.f - 2.f * ((k >> 1) & 1);
        float s5v = 1.f - 2.f * (k & 1);
        float s2v = 1.f - 2.f * (float)q2b;
        float s6v = 1.f - 2.f * (float)t8;
        const float* ph = phi + 16;
        float ang = __ldg(&ph[2]) * s2v * s3v + __ldg(&ph[3]) * s3v * s4v
                  + __ldg(&ph[4]) * s4v * s5v + __ldg(&ph[5]) * s5v * s6v;
        float c0, s0;
        sincosf(0.5f * ang, &s0, &c0);
        g_DjARe[i]  = bc2(c0);
        g_DjAIm[i]  = bc2(-s0);
        g_DjAImN[i] = bc2(s0);
    }
}

// ---------------- packed 2x2 gate on 8-value register subcube ----------------
template<int VB>
__device__ __forceinline__ void gate8(ull* ar, ull* ai, const ull* u)
{
    ull u00x = u[0], u00y = u[1],  u00yn = u[2];
    ull u01x = u[3], u01y = u[4],  u01yn = u[5];
    ull u10x = u[6], u10y = u[7],  u10yn = u[8];
    ull u11x = u[9], u11y = u[10], u11yn = u[11];
    #pragma unroll
    for (int m = 0; m < 8; m++) {
        if (m & (1 << VB)) continue;
        int m1 = m | (1 << VB);
        ull axr = ar[m],  axi = ai[m];
        ull bxr = ar[m1], bxi = ai[m1];
        ar[m]  = f2fma(u00x, axr, f2fma(u00yn, axi, f2fma(u01x, bxr, f2mul(u01yn, bxi))));
        ai[m]  = f2fma(u00x, axi, f2fma(u00y,  axr, f2fma(u01x, bxi, f2mul(u01y,  bxr))));
        ar[m1] = f2fma(u10x, axr, f2fma(u10yn, axi, f2fma(u11x, bxr, f2mul(u11yn, bxi))));
        ai[m1] = f2fma(u10x, axi, f2fma(u10y,  axr, f2fma(u11x, bxi, f2mul(u11y,  bxr))));
    }
}

// ---------------- unified pass kernel (pi = 0..4) ----------------
extern "C" __global__ void __launch_bounds__(512, 2)
pass_kernel(int pi)
{
    extern __shared__ ull smem[];           // 4096 + 4096 (passes 0..3 only)
    ull* sre = smem;
    ull* sim = smem + 4096;
    __shared__ ull sR[108];
    __shared__ ull sCk[36], sDf[36], sLn[6];
    __shared__ ull sDjR[16], sDjI[16], sDjN[16];
    __shared__ float wsum[16][16];

    const int t    = threadIdx.x;
    const int tile = blockIdx.x;            // 3 block bits
    const int b    = blockIdx.y;
    const bool covB = (pi == 1 || pi == 3);
    const bool fin  = (pi == 4);
    const int base = b * 32768 + (covB ? (tile << 9) : (tile << 12));
    const int kstr = covB ? 4096 : 512;

    if (!fin) {
        if (t < 108) sR[t] = g_Rnd[pi * 108 + t];
        if (t >= 128 && t < 164) sCk[t - 128] = g_OwnCk[pi * 36 + (t - 128)];
        if (t >= 192 && t < 198) sLn[t - 192] = g_Lane[pi * 6 + (t - 192)];
    }
    if (pi > 0) {
        if (t >= 224 && t < 260) sDf[t - 224] = g_Def[(pi - 1) * 36 + (t - 224)];
        if (pi == 1 || pi == 3) {
            int s3 = (tile >> 2) & 1, lh = (pi - 1) >> 1;
            if (t >= 288 && t < 296)
                { int k = t - 288; sDjR[k] = g_DjBRe[lh*16 + s3*8 + k];
                  sDjI[k] = g_DjBIm[lh*16 + s3*8 + k]; sDjN[k] = g_DjBImN[lh*16 + s3*8 + k]; }
        } else if (pi == 2) {
            int q2b = tile & 1;
            if (t >= 288 && t < 304)
                { int i = t - 288; int k = i >> 1, t8 = i & 1;
                  int gi = k*4 + q2b*2 + t8;
                  sDjR[i] = g_DjARe[gi]; sDjI[i] = g_DjAIm[gi]; sDjN[i] = g_DjAImN[gi]; }
        }
    }
    __syncthreads();

    // ---- chunk phase: registers hold the 8 k-slabs ----
    ull vr[8], vi[8];
    if (pi == 0) {
        #pragma unroll
        for (int k = 0; k < 8; k++) {
            int p = (tile << 12) | (k << 9) | t;
            float t1 = g_T1[b * 256 + (p >> 7)];
            ull  t0 = g_T0u[b * 128 + (t & 127)];
            vr[k] = f2mul(bc2(t1), t0);
            vi[k] = 0ull;
        }
    } else {
        #pragma unroll
        for (int k = 0; k < 8; k++) {
            vr[k] = g_re[base + k * kstr + t];
            vi[k] = g_im[base + k * kstr + t];
        }
        // deferred gates from layer pi-1 (on k bits)
        gate8<0>(vr, vi, &sDf[0]);
        gate8<1>(vr, vi, &sDf[12]);
        gate8<2>(vr, vi, &sDf[24]);
        // deferred diagonal
        if (pi == 1 || pi == 3) {
            #pragma unroll
            for (int k = 0; k < 8; k++) {
                ull cr = sDjR[k], ci = sDjI[k], cin = sDjN[k];
                ull nr = f2fma(cr, vr[k], f2mul(cin, vi[k]));
                vi[k]  = f2fma(cr, vi[k], f2mul(ci,  vr[k]));
                vr[k]  = nr;
            }
        } else if (pi == 2) {
            int t8 = (t >> 8) & 1;
            #pragma unroll
            for (int k = 0; k < 8; k++) {
                int i = k * 2 + t8;
                ull cr = sDjR[i], ci = sDjI[i], cin = sDjN[i];
                ull nr = f2fma(cr, vr[k], f2mul(cin, vi[k]));
                vi[k]  = f2fma(cr, vi[k], f2mul(ci,  vr[k]));
                vr[k]  = nr;
            }
        }
    }

    if (fin) {
        // ---- expectations ----
        float ptl0 = 0.f, ptl1 = 0.f, a3 = 0.f, a4 = 0.f, a5 = 0.f;
        #pragma unroll
        for (int k = 0; k < 8; k++) {
            ull pp = f2fma(vr[k], vr[k], f2mul(vi[k], vi[k]));
            float l0, l1; up2(pp, l0, l1);
            float pj = l0 + l1;
            ptl0 += l0; ptl1 += l1;
            a3 += ((k >> 2) & 1) ? -pj : pj;
            a4 += ((k >> 1) & 1) ? -pj : pj;
            a5 += ( k       & 1) ? -pj : pj;
        }
        float pt = ptl0 + ptl1;
        float acc[16];
        acc[0] = ((tile >> 2) & 1) ? -pt : pt;
        acc[1] = ((tile >> 1) & 1) ? -pt : pt;
        acc[2] = ( tile       & 1) ? -pt : pt;
        acc[3] = a3; acc[4] = a4; acc[5] = a5;
        #pragma unroll
        for (int q = 6; q < 15; q++)
            acc[q] = ((t >> (14 - q)) & 1) ? -pt : pt;
        acc[15] = ptl0 - ptl1;

        #pragma unroll
        for (int q = 0; q < 16; q++) {
            float v = acc[q];
            #pragma unroll
            for (int o = 16; o > 0; o >>= 1)
                v += __shfl_down_sync(0xffffffffu, v, o);
            if ((t & 31) == 0) wsum[t >> 5][q] = v;
        }
        __syncthreads();
        if (t < 16) {
            float v = 0.f;
            #pragma unroll
            for (int w = 0; w < 16; w++) v += wsum[w][t];
            g_zpart[(b * 8 + tile) * 16 + t] = v;
        }
        return;
    }

    // ---- own layer: lane gate + chunk gates ----
    {
        ull P1 = sLn[0], P2 = sLn[1], P3 = sLn[2], P4 = sLn[3], P5 = sLn[4], P6 = sLn[5];
        #pragma unroll
        for (int m = 0; m < 8; m++) {
            ull sar = swap2(vr[m]), sai = swap2(vi[m]);
            ull nr = f2fma(P1, vr[m], f2fma(P2, sar, f2fma(P3, vi[m], f2mul(P4, sai))));
            ull ni = f2fma(P1, vi[m], f2fma(P2, sai, f2fma(P5, vr[m], f2mul(P6, sar))));
            vr[m] = nr; vi[m] = ni;
        }
    }
    gate8<0>(vr, vi, &sCk[0]);
    gate8<1>(vr, vi, &sCk[12]);
    gate8<2>(vr, vi, &sCk[24]);

    #pragma unroll
    for (int k = 0; k < 8; k++) {
        int s = swz(k * 512 + t);
        sre[s] = vr[k];
        sim[s] = vi[k];
    }
    __syncthreads();

    // ---- round A: u bits 6,7,8 ----
    {
        ull ar[8], ai[8];
        int pre = ((t >> 6) << 9) | (t & 63);
        int idxs[8];
        #pragma unroll
        for (int j = 0; j < 8; j++) idxs[j] = pre | (j << 6);
        #pragma unroll
        for (int j = 0; j < 8; j++) {
            int sp = swz(idxs[j]);
            ar[j] = sre[sp]; ai[j] = sim[sp];
        }
        gate8<0>(ar, ai, &sR[72]);
        gate8<1>(ar, ai, &sR[84]);
        gate8<2>(ar, ai, &sR[96]);
        #pragma unroll
        for (int j = 0; j < 8; j++) {
            int sp = swz(idxs[j]);
            sre[sp] = ar[j]; sim[sp] = ai[j];
        }
    }
    __syncthreads();

    // ---- round B: u bits 3,4,5 ----
    {
        ull ar[8], ai[8];
        int pre = ((t >> 3) << 6) | (t & 7);
        int idxs[8];
        #pragma unroll
        for (int j = 0; j < 8; j++) idxs[j] = pre | (j << 3);
        #pragma unroll
        for (int j = 0; j < 8; j++) {
            int sp = swz(idxs[j]);
            ar[j] = sre[sp]; ai[j] = sim[sp];
        }
        gate8<0>(ar, ai, &sR[36]);
        gate8<1>(ar, ai, &sR[48]);
        gate8<2>(ar, ai, &sR[60]);
        #pragma unroll
        for (int j = 0; j < 8; j++) {
            int sp = swz(idxs[j]);
            sre[sp] = ar[j]; sim[sp] = ai[j];
        }
    }
    __syncthreads();

    // ---- round C (fused): u bits 0,1,2 + Ep diag + vector store ----
    {
        ull ar[8], ai[8];
        int ub = t << 3;
        #pragma unroll
        for (int e = 0; e < 8; e++) {
            int sp = swz(ub | e);
            ar[e] = sre[sp]; ai[e] = sim[sp];
        }
        gate8<0>(ar, ai, &sR[0]);
        gate8<1>(ar, ai, &sR[12]);
        gate8<2>(ar, ai, &sR[24]);

        if (pi < 3) {
            const ulonglong2* ER = reinterpret_cast<const ulonglong2*>(g_EpRe)  + pi * 2048 + (ub >> 1);
            const ulonglong2* EI = reinterpret_cast<const ulonglong2*>(g_EpIm)  + pi * 2048 + (ub >> 1);
            const ulonglong2* EN = reinterpret_cast<const ulonglong2*>(g_EpImN) + pi * 2048 + (ub >> 1);
            #pragma unroll
            for (int e2 = 0; e2 < 4; e2++) {
                ulonglong2 cr = ER[e2], ci = EI[e2], cn = EN[e2];
                int e = 2 * e2;
                ull nr0 = f2fma(cr.x, ar[e], f2mul(cn.x, ai[e]));
                ai[e]   = f2fma(cr.x, ai[e], f2mul(ci.x, ar[e]));
                ar[e]   = nr0;
                ull nr1 = f2fma(cr.y, ar[e+1], f2mul(cn.y, ai[e+1]));
                ai[e+1] = f2fma(cr.y, ai[e+1], f2mul(ci.y, ar[e+1]));
                ar[e+1] = nr1;
            }
        }

        ulonglong2* R2 = reinterpret_cast<ulonglong2*>(g_re);
        ulonglong2* I2 = reinterpret_cast<ulonglong2*>(g_im);
        int a2;
        if (covB) a2 = (base >> 1) + ((t >> 6) << 11) + ((t & 63) << 2);
        else      a2 = (base + ub) >> 1;
        #pragma unroll
        for (int e2 = 0; e2 < 4; e2++) {
            R2[a2 + e2] = make_ulonglong2(ar[2*e2], ar[2*e2+1]);
            I2[a2 + e2] = make_ulonglong2(ai[2*e2], ai[2*e2+1]);
        }
    }
}

// ---------------- final reduce + MLP ----------------
__global__ void final_kernel(const float* __restrict__ W1, const float* __restrict__ b1,
                             const float* __restrict__ W2, const float* __restrict__ b2,
                             float* __restrict__ out)
{
    int t = threadIdx.x;
    int warp = t >> 5, lane = t & 31;
    int b = blockIdx.x * 8 + warp;

    float z = 0.f;
    if (lane < 16) {
        #pragma unroll
        for (int c = 0; c < 8; c++) z += g_zpart[(b * 8 + c) * 16 + lane];
    }
    float h = b1[lane];
    #pragma unroll
    for (int q = 0; q < 16; q++) {
        float zq = __shfl_sync(0xffffffffu, z, q);
        h += zq * W1[q * 32 + lane];
    }
    h = fmaxf(h, 0.f);

    float o = (lane < OUTD) ? b2[lane] : 0.f;
    #pragma unroll
    for (int j = 0; j < 32; j++) {
        float hj = __shfl_sync(0xffffffffu, h, j);
        if (lane < OUTD) o += hj * W2[j * OUTD + lane];
    }
    if (lane < OUTD) out[b * OUTD + lane] = o;
}

// ---------------- launch ----------------
extern "C" void kernel_launch(void* const* d_in, const int* in_sizes, int n_in,
                              void* d_out, int out_size)
{
    const float* x     = (const float*)d_in[0];
    const float* W_enc = (const float*)d_in[1];
    const float* b_enc = (const float*)d_in[2];
    const float* theta = (const float*)d_in[3];
    const float* phi   = (const float*)d_in[4];
    const float* W1    = (const float*)d_in[5];
    const float* b1    = (const float*)d_in[6];
    const float* W2    = (const float*)d_in[7];
    const float* b2    = (const float*)d_in[8];
    float* out = (float*)d_out;

    cudaFuncSetAttribute((const void*)pass_kernel,
                         cudaFuncAttributeMaxDynamicSharedMemorySize, 65536);

    prep_kernel<<<256, 256>>>(x, W_enc, b_enc, theta);
    ep_kernel<<<12, 1024>>>(phi);
    dj_kernel<<<1, 64>>>(phi);

    for (int pi = 0; pi < 5; pi++)
        pass_kernel<<<dim3(8, 256), 512, (pi == 4) ? 0 : 65536>>>(pi);

    final_kernel<<<32, 256>>>(W1, b1, W2, b2, out);
}

// round 13
// speedup vs baseline: 1.4296x; 1.4296x over previous
#include <cuda_runtime.h>
#include <math.h>

#define NQ       16
#define BATCH    256
#define NL       4
#define DIN      512
#define OUTD     10

typedef unsigned long long ull;

// ---------------- scratch (SoA state, packed across amp bit 0 = qubit 15) ----------------
__device__ __align__(16) ull g_re[BATCH * 32768];        // 64 MB re pairs
__device__ __align__(16) ull g_im[BATCH * 32768];        // 64 MB im pairs
__device__ ull   g_T0u[BATCH * 128];
__device__ float g_T1[BATCH * 256];
__device__ ull   g_Rnd[NL * 9 * 12];         // round gates: [l][ubit 0..8] -> qubit 14-ubit
__device__ ull   g_OwnCk[NL * 3 * 12];       // own chunk gates: [pi][kbit]
__device__ ull   g_Def[NL * 3 * 12];         // deferred gates: [slot=layer][kbit]
__device__ ull   g_Lane[NL * 6];             // lane (q15) gate consts
__device__ __align__(16) ull g_EpRe[3 * 4096], g_EpIm[3 * 4096], g_EpImN[3 * 4096];
__device__ ull   g_DjBRe[2*16], g_DjBIm[2*16], g_DjBImN[2*16];  // [l/2][s3][k] layers 0,2
__device__ ull   g_DjARe[32],  g_DjAIm[32],  g_DjAImN[32];      // [k][q2b][t8] layer 1
__device__ float g_zpart[BATCH * 8 * 16];

// ---------------- f32x2 helpers ----------------
__device__ __forceinline__ ull pk2(float lo, float hi) {
    ull r; asm("mov.b64 %0, {%1, %2};" : "=l"(r) : "f"(lo), "f"(hi)); return r;
}
__device__ __forceinline__ ull bc2(float v) {
    ull r; asm("mov.b64 %0, {%1, %1};" : "=l"(r) : "f"(v)); return r;
}
__device__ __forceinline__ void up2(ull v, float& lo, float& hi) {
    asm("mov.b64 {%0, %1}, %2;" : "=f"(lo), "=f"(hi) : "l"(v));
}
__device__ __forceinline__ ull f2fma(ull a, ull b, ull c) {
    ull d; asm("fma.rn.f32x2 %0, %1, %2, %3;" : "=l"(d) : "l"(a), "l"(b), "l"(c)); return d;
}
__device__ __forceinline__ ull f2mul(ull a, ull b) {
    ull d; asm("mul.rn.f32x2 %0, %1, %2;" : "=l"(d) : "l"(a), "l"(b)); return d;
}
__device__ __forceinline__ ull swap2(ull v) {
    float lo, hi; up2(v, lo, hi); return pk2(hi, lo);
}
// swizzle verified conflict-free for chunk (i=m<<8|t), round1 (i=t<<4|m), round2 (i=hi<<8|m<<4|lo)
__device__ __forceinline__ int swz(int i) { return i ^ (((i >> 3) ^ (i >> 7)) & 15); }

// ---------------- prep ----------------
__global__ void prep_kernel(const float* __restrict__ x,
                            const float* __restrict__ W_enc,
                            const float* __restrict__ b_enc,
                            const float* __restrict__ theta)
{
    __shared__ float partial[256];
    __shared__ float cs[NQ], ss[NQ];
    __shared__ float2 Ush[NL * NQ * 4];

    int b   = blockIdx.x;
    int tid = threadIdx.x;
    int q   = tid & 15;
    int seg = tid >> 4;

    {
        float acc = 0.f;
        const float* xb = x + b * DIN;
        int d0 = seg * 32;
        #pragma unroll 8
        for (int d = d0; d < d0 + 32; d++)
            acc += xb[d] * W_enc[d * NQ + q];
        partial[tid] = acc;
    }
    __syncthreads();
    if (tid < NQ) {
        float s = b_enc[tid];
        #pragma unroll
        for (int g = 0; g < 16; g++) s += partial[g * 16 + tid];
        float ang = tanhf(s) * 3.14159265358979323846f;
        cs[tid] = cosf(0.5f * ang);
        ss[tid] = sinf(0.5f * ang);
    }
    __syncthreads();

    {
        int m = tid;
        float p0 = 1.f, p1 = 1.f;
        #pragma unroll
        for (int k = 0; k < 8; k++) {
            int bit = (m >> k) & 1;
            p0 *= bit ? ss[15 - k] : cs[15 - k];
            p1 *= bit ? ss[7 - k]  : cs[7 - k];
        }
        ((float*)g_T0u)[b * 256 + m] = p0;
        g_T1[b * 256 + m] = p1;
    }

    if (b == 0) {
        if (tid < NL * NQ) {
            int l = tid >> 4, qq = tid & 15;
            const float* th = theta + (l * NQ + qq) * 3;
            float a0 = th[0], a1 = th[1], a2 = th[2];
            float ca = cosf(0.5f * a0), sa = sinf(0.5f * a0);
            float cb = cosf(0.5f * a1), sb = sinf(0.5f * a1);
            float cz = cosf(0.5f * a2), sz = sinf(0.5f * a2);
            float2 em = make_float2(cz, -sz);
            float2 ep = make_float2(cz,  sz);
            float2 r00 = make_float2( cb * em.x,  cb * em.y);
            float2 r01 = make_float2(-sb * ep.x, -sb * ep.y);
            float2 r10 = make_float2( sb * em.x,  sb * em.y);
            float2 r11 = make_float2( cb * ep.x,  cb * ep.y);
            float2 u00 = make_float2(ca * r00.x + sa * r10.y, ca * r00.y - sa * r10.x);
            float2 u01 = make_float2(ca * r01.x + sa * r11.y, ca * r01.y - sa * r11.x);
            float2 u10 = make_float2(sa * r00.y + ca * r10.x, -sa * r00.x + ca * r10.y);
            float2 u11 = make_float2(sa * r01.y + ca * r11.x, -sa * r01.x + ca * r11.y);
            int base = tid * 4;
            Ush[base + 0] = u00; Ush[base + 1] = u01;
            Ush[base + 2] = u10; Ush[base + 3] = u11;
        }
        __syncthreads();

        // round gates: [l][ubit][12], ubit 0..8 -> qubit 14-ubit
        for (int k = tid; k < NL * 108; k += 256) {
            int l = k / 108, rem = k % 108, ub = rem / 12, e = rem % 12;
            int j2 = e / 3, kind = e % 3;
            float2 u = Ush[(l * 16 + (14 - ub)) * 4 + j2];
            float v = (kind == 0) ? u.x : ((kind == 1) ? u.y : -u.y);
            g_Rnd[k] = bc2(v);
        }
        // own chunk gates: [pi][kbit][12]; covA(pi even): q = 5-kbit; covB: q = 2-kbit
        for (int k = tid; k < NL * 36; k += 256) {
            int pi = k / 36, rem = k % 36, kb = rem / 12, e = rem % 12;
            int qq = ((pi & 1) ? 2 : 5) - kb;
            int j2 = e / 3, kind = e % 3;
            float2 u = Ush[(pi * 16 + qq) * 4 + j2];
            float v = (kind == 0) ? u.x : ((kind == 1) ? u.y : -u.y);
            g_OwnCk[k] = bc2(v);
        }
        // deferred gates: [slot=s][kbit][12]; s even: q = 2-kbit; s odd: q = 5-kbit
        for (int k = tid; k < NL * 36; k += 256) {
            int s = k / 36, rem = k % 36, kb = rem / 12, e = rem % 12;
            int qq = ((s & 1) ? 5 : 2) - kb;
            int j2 = e / 3, kind = e % 3;
            float2 u = Ush[(s * 16 + qq) * 4 + j2];
            float v = (kind == 0) ? u.x : ((kind == 1) ? u.y : -u.y);
            g_Def[k] = bc2(v);
        }
        // lane gate (qubit 15)
        if (tid < NL) {
            int l = tid;
            float2 u00 = Ush[(l * 16 + 15) * 4 + 0];
            float2 u01 = Ush[(l * 16 + 15) * 4 + 1];
            float2 u10 = Ush[(l * 16 + 15) * 4 + 2];
            float2 u11 = Ush[(l * 16 + 15) * 4 + 3];
            g_Lane[l * 6 + 0] = pk2(u00.x, u11.x);
            g_Lane[l * 6 + 1] = pk2(u01.x, u10.x);
            g_Lane[l * 6 + 2] = pk2(-u00.y, -u11.y);
            g_Lane[l * 6 + 3] = pk2(-u01.y, -u10.y);
            g_Lane[l * 6 + 4] = pk2(u00.y, u11.y);
            g_Lane[l * 6 + 5] = pk2(u01.y, u10.y);
        }
    }
}

// ---------------- Ep tables: per-pass epilogue diagonal (passes 0,1,2) ----------------
__global__ void ep_kernel(const float* __restrict__ phi)
{
    int gid = blockIdx.x * 1024 + threadIdx.x;   // 3*4096
    int pi = gid >> 12, u = gid & 4095;
    float ang = 0.f, lp;
    if (pi == 1) {
        #pragma unroll
        for (int bb = 0; bb < 8; bb++) {
            float sA = 1.f - 2.f * ((u >> (bb + 1)) & 1);
            float sB = 1.f - 2.f * ((u >> bb) & 1);
            ang += __ldg(&phi[16 + 13 - bb]) * sA * sB;
        }
        float sq0 = 1.f - 2.f * ((u >> 11) & 1);
        float sq1 = 1.f - 2.f * ((u >> 10) & 1);
        float sq2 = 1.f - 2.f * ((u >> 9) & 1);
        ang += __ldg(&phi[16 + 0]) * sq0 * sq1 + __ldg(&phi[16 + 1]) * sq1 * sq2;
        lp = __ldg(&phi[16 + 14]) * (1.f - 2.f * (u & 1)) + __ldg(&phi[16 + 15]) * sq0;
    } else {
        int l = pi;
        #pragma unroll
        for (int bb = 0; bb < 11; bb++) {
            float sA = 1.f - 2.f * ((u >> (bb + 1)) & 1);
            float sB = 1.f - 2.f * ((u >> bb) & 1);
            ang += __ldg(&phi[l * 16 + 13 - bb]) * sA * sB;
        }
        lp = __ldg(&phi[l * 16 + 14]) * (1.f - 2.f * (u & 1));
    }
    float a0 = ang + lp, a1 = ang - lp;
    float c0, s0, c1, s1;
    sincosf(0.5f * a0, &s0, &c0);
    sincosf(0.5f * a1, &s1, &c1);
    g_EpRe[gid]  = pk2(c0, c1);
    g_EpIm[gid]  = pk2(-s0, -s1);
    g_EpImN[gid] = pk2(s0, s1);
}

// ---------------- Dj tables ----------------
__global__ void dj_kernel(const float* __restrict__ phi)
{
    int tid = threadIdx.x;   // 64
    if (tid < 32) {
        int i = tid;
        int lh = i >> 4, l = lh * 2, s3i = (i >> 3) & 1, k = i & 7;
        float s0v = 1.f - 2.f * ((k >> 2) & 1);
        float s1v = 1.f - 2.f * ((k >> 1) & 1);
        float s2v = 1.f - 2.f * (k & 1);
        float s3v = 1.f - 2.f * (float)s3i;
        const float* ph = phi + l * 16;
        float ang = __ldg(&ph[0]) * s0v * s1v + __ldg(&ph[1]) * s1v * s2v + __ldg(&ph[2]) * s2v * s3v;
        float C = __ldg(&ph[15]) * s0v;
        float a0 = ang + C, a1 = ang - C;
        float c0, s0, c1, s1;
        sincosf(0.5f * a0, &s0, &c0);
        sincosf(0.5f * a1, &s1, &c1);
        g_DjBRe[i]  = pk2(c0, c1);
        g_DjBIm[i]  = pk2(-s0, -s1);
        g_DjBImN[i] = pk2(s0, s1);
    } else {
        int i = tid - 32;
        int k = i >> 2, q2b = (i >> 1) & 1, t8 = i & 1;
        float s3v = 1.f - 2.f * ((k >> 2) & 1);
        float s4v = 1.f - 2.f * ((k >> 1) & 1);
        float s5v = 1.f - 2.f * (k & 1);
        float s2v = 1.f - 2.f * (float)q2b;
        float s6v = 1.f - 2.f * (float)t8;
        const float* ph = phi + 16;
        float ang = __ldg(&ph[2]) * s2v * s3v + __ldg(&ph[3]) * s3v * s4v
                  + __ldg(&ph[4]) * s4v * s5v + __ldg(&ph[5]) * s5v * s6v;
        float c0, s0;
        sincosf(0.5f * ang, &s0, &c0);
        g_DjARe[i]  = bc2(c0);
        g_DjAIm[i]  = bc2(-s0);
        g_DjAImN[i] = bc2(s0);
    }
}

// ---------------- packed 2x2 gate on 16-value register subcube ----------------
template<int VB>
__device__ __forceinline__ void gate16(ull* ar, ull* ai, const ull* u)
{
    ull u00x = u[0], u00y = u[1],  u00yn = u[2];
    ull u01x = u[3], u01y = u[4],  u01yn = u[5];
    ull u10x = u[6], u10y = u[7],  u10yn = u[8];
    ull u11x = u[9], u11y = u[10], u11yn = u[11];
    #pragma unroll
    for (int m = 0; m < 16; m++) {
        if (m & (1 << VB)) continue;
        int m1 = m | (1 << VB);
        ull axr = ar[m],  axi = ai[m];
        ull bxr = ar[m1], bxi = ai[m1];
        ar[m]  = f2fma(u00x, axr, f2fma(u00yn, axi, f2fma(u01x, bxr, f2mul(u01yn, bxi))));
        ai[m]  = f2fma(u00x, axi, f2fma(u00y,  axr, f2fma(u01x, bxi, f2mul(u01y,  bxr))));
        ar[m1] = f2fma(u10x, axr, f2fma(u10yn, axi, f2fma(u11x, bxr, f2mul(u11yn, bxi))));
        ai[m1] = f2fma(u10x, axi, f2fma(u10y,  axr, f2fma(u11x, bxi, f2mul(u11y,  bxr))));
    }
}

// ---------------- unified pass kernel (pi = 0..4); 256 thr x 16 elems ----------------
extern "C" __global__ void __launch_bounds__(256, 2)
pass_kernel(int pi)
{
    extern __shared__ ull smem[];           // 4096 + 4096 (passes 0..3)
    ull* sre = smem;
    ull* sim = smem + 4096;
    __shared__ ull sR[108];
    __shared__ ull sCk[36], sDf[36], sLn[6];
    __shared__ ull sDjR[16], sDjI[16], sDjN[16];
    __shared__ float wsum[8][16];

    const int t    = threadIdx.x;           // 0..255
    const int tile = blockIdx.x;            // 3 block bits
    const int b    = blockIdx.y;
    const bool covB = (pi == 1 || pi == 3);
    const bool fin  = (pi == 4);
    const int base = b * 32768 + (covB ? (tile << 9) : (tile << 12));

    if (!fin) {
        if (t < 108)               sR[t]        = g_Rnd[pi * 108 + t];
        else if (t < 144)          sCk[t - 108] = g_OwnCk[pi * 36 + (t - 108)];
        else if (t < 150)          sLn[t - 144] = g_Lane[pi * 6 + (t - 144)];
    }
    if (pi > 0) {
        if (t >= 160 && t < 196) sDf[t - 160] = g_Def[(pi - 1) * 36 + (t - 160)];
        if (pi == 1 || pi == 3) {
            int s3 = (tile >> 2) & 1, lh = (pi - 1) >> 1;
            if (t >= 200 && t < 208) {
                int k = t - 200;
                sDjR[k] = g_DjBRe[lh * 16 + s3 * 8 + k];
                sDjI[k] = g_DjBIm[lh * 16 + s3 * 8 + k];
                sDjN[k] = g_DjBImN[lh * 16 + s3 * 8 + k];
            }
        } else if (pi == 2) {
            int q2b = tile & 1;
            if (t >= 200 && t < 216) {
                int i = t - 200, k = i >> 1, t8 = i & 1;
                int gi = k * 4 + q2b * 2 + t8;
                sDjR[i] = g_DjARe[gi]; sDjI[i] = g_DjAIm[gi]; sDjN[i] = g_DjAImN[gi];
            }
        }
    }
    __syncthreads();

    // ---- chunk phase: m = u bits 8..11 (bit0 -> q6; bits 1,2,3 -> chunk qubits) ----
    ull vr[16], vi[16];
    if (pi == 0) {
        ull t0 = g_T0u[b * 128 + (t & 127)];
        #pragma unroll
        for (int m = 0; m < 16; m++) {
            int p = (tile << 12) | (m << 8) | t;
            float t1 = g_T1[b * 256 + (p >> 7)];
            vr[m] = f2mul(bc2(t1), t0);
            vi[m] = 0ull;
        }
    } else {
        #pragma unroll
        for (int m = 0; m < 16; m++) {
            int off = covB ? (((m >> 1) << 12) | ((m & 1) << 8) | t)
                           : ((m << 8) | t);
            vr[m] = g_re[base + off];
            vi[m] = g_im[base + off];
        }
        // deferred gates (layer pi-1) on m bits 1,2,3
        gate16<1>(vr, vi, &sDf[0]);
        gate16<2>(vr, vi, &sDf[12]);
        gate16<3>(vr, vi, &sDf[24]);
        // deferred diagonal
        if (pi == 1 || pi == 3) {
            #pragma unroll
            for (int m = 0; m < 16; m++) {
                int k = m >> 1;
                ull cr = sDjR[k], ci = sDjI[k], cin = sDjN[k];
                ull nr = f2fma(cr, vr[m], f2mul(cin, vi[m]));
                vi[m]  = f2fma(cr, vi[m], f2mul(ci,  vr[m]));
                vr[m]  = nr;
            }
        } else if (pi == 2) {
            #pragma unroll
            for (int m = 0; m < 16; m++) {
                ull cr = sDjR[m], ci = sDjI[m], cin = sDjN[m];
                ull nr = f2fma(cr, vr[m], f2mul(cin, vi[m]));
                vi[m]  = f2fma(cr, vi[m], f2mul(ci,  vr[m]));
                vr[m]  = nr;
            }
        }
    }

    if (fin) {
        // ---- expectations ----
        float ptl0 = 0.f, ptl1 = 0.f, a3 = 0.f, a4 = 0.f, a5 = 0.f, a6 = 0.f;
        #pragma unroll
        for (int m = 0; m < 16; m++) {
            ull pp = f2fma(vr[m], vr[m], f2mul(vi[m], vi[m]));
            float l0, l1; up2(pp, l0, l1);
            float pj = l0 + l1;
            ptl0 += l0; ptl1 += l1;
            a3 += ((m >> 3) & 1) ? -pj : pj;   // q3 = m bit3
            a4 += ((m >> 2) & 1) ? -pj : pj;   // q4 = m bit2
            a5 += ((m >> 1) & 1) ? -pj : pj;   // q5 = m bit1
            a6 += ( m       & 1) ? -pj : pj;   // q6 = m bit0
        }
        float pt = ptl0 + ptl1;
        float acc[16];
        acc[0] = ((tile >> 2) & 1) ? -pt : pt;
        acc[1] = ((tile >> 1) & 1) ? -pt : pt;
        acc[2] = ( tile       & 1) ? -pt : pt;
        acc[3] = a3; acc[4] = a4; acc[5] = a5; acc[6] = a6;
        #pragma unroll
        for (int q = 7; q < 15; q++)
            acc[q] = ((t >> (14 - q)) & 1) ? -pt : pt;   // q7..q14 from t bits 7..0
        acc[15] = ptl0 - ptl1;

        #pragma unroll
        for (int q = 0; q < 16; q++) {
            float v = acc[q];
            #pragma unroll
            for (int o = 16; o > 0; o >>= 1)
                v += __shfl_down_sync(0xffffffffu, v, o);
            if ((t & 31) == 0) wsum[t >> 5][q] = v;
        }
        __syncthreads();
        if (t < 16) {
            float v = 0.f;
            #pragma unroll
            for (int w = 0; w < 8; w++) v += wsum[w][t];
            g_zpart[(b * 8 + tile) * 16 + t] = v;
        }
        return;
    }

    // ---- own layer in chunk phase: lane + chunk gates + q6 ----
    {
        ull P1 = sLn[0], P2 = sLn[1], P3 = sLn[2], P4 = sLn[3], P5 = sLn[4], P6 = sLn[5];
        #pragma unroll
        for (int m = 0; m < 16; m++) {
            ull sar = swap2(vr[m]), sai = swap2(vi[m]);
            ull nr = f2fma(P1, vr[m], f2fma(P2, sar, f2fma(P3, vi[m], f2mul(P4, sai))));
            ull ni = f2fma(P1, vi[m], f2fma(P2, sai, f2fma(P5, vr[m], f2mul(P6, sar))));
            vr[m] = nr; vi[m] = ni;
        }
    }
    gate16<1>(vr, vi, &sCk[0]);
    gate16<2>(vr, vi, &sCk[12]);
    gate16<3>(vr, vi, &sCk[24]);
    gate16<0>(vr, vi, &sR[96]);        // q6 (u bit 8)

    #pragma unroll
    for (int m = 0; m < 16; m++) {
        int s = swz((m << 8) | t);
        sre[s] = vr[m];
        sim[s] = vi[m];
    }
    __syncthreads();

    // ---- round 1: m = u bits 0..3 (q14,q13,q12,q11) ----
    {
        ull ar[16], ai[16];
        #pragma unroll
        for (int m = 0; m < 16; m++) {
            int s = swz((t << 4) | m);
            ar[m] = sre[s]; ai[m] = sim[s];
        }
        gate16<0>(ar, ai, &sR[0]);
        gate16<1>(ar, ai, &sR[12]);
        gate16<2>(ar, ai, &sR[24]);
        gate16<3>(ar, ai, &sR[36]);
        #pragma unroll
        for (int m = 0; m < 16; m++) {
            int s = swz((t << 4) | m);
            sre[s] = ar[m]; sim[s] = ai[m];
        }
    }
    __syncthreads();

    // ---- round 2: m = u bits 4..7 (q10,q9,q8,q7) + Ep diag + global store ----
    {
        ull ar[16], ai[16];
        int hi = t >> 4, lo = t & 15;
        #pragma unroll
        for (int m = 0; m < 16; m++) {
            int s = swz((hi << 8) | (m << 4) | lo);
            ar[m] = sre[s]; ai[m] = sim[s];
        }
        gate16<0>(ar, ai, &sR[48]);
        gate16<1>(ar, ai, &sR[60]);
        gate16<2>(ar, ai, &sR[72]);
        gate16<3>(ar, ai, &sR[84]);

        if (pi < 3) {
            const ull* ER = g_EpRe  + pi * 4096;
            const ull* EI = g_EpIm  + pi * 4096;
            const ull* EN = g_EpImN + pi * 4096;
            #pragma unroll
            for (int m = 0; m < 16; m++) {
                int u = (hi << 8) | (m << 4) | lo;
                ull cr = __ldg(&ER[u]), ci = __ldg(&EI[u]), cin = __ldg(&EN[u]);
                ull nr = f2fma(cr, ar[m], f2mul(cin, ai[m]));
                ai[m]  = f2fma(cr, ai[m], f2mul(ci,  ar[m]));
                ar[m]  = nr;
            }
        }

        #pragma unroll
        for (int m = 0; m < 16; m++) {
            int u = (hi << 8) | (m << 4) | lo;
            int off = covB ? ((u & 511) | ((u >> 9) << 12)) : u;
            g_re[base + off] = ar[m];
            g_im[base + off] = ai[m];
        }
    }
}

// ---------------- final reduce + MLP ----------------
__global__ void final_kernel(const float* __restrict__ W1, const float* __restrict__ b1,
                             const float* __restrict__ W2, const float* __restrict__ b2,
                             float* __restrict__ out)
{
    int t = threadIdx.x;
    int warp = t >> 5, lane = t & 31;
    int b = blockIdx.x * 8 + warp;

    float z = 0.f;
    if (lane < 16) {
        #pragma unroll
        for (int c = 0; c < 8; c++) z += g_zpart[(b * 8 + c) * 16 + lane];
    }
    float h = b1[lane];
    #pragma unroll
    for (int q = 0; q < 16; q++) {
        float zq = __shfl_sync(0xffffffffu, z, q);
        h += zq * W1[q * 32 + lane];
    }
    h = fmaxf(h, 0.f);

    float o = (lane < OUTD) ? b2[lane] : 0.f;
    #pragma unroll
    for (int j = 0; j < 32; j++) {
        float hj = __shfl_sync(0xffffffffu, h, j);
        if (lane < OUTD) o += hj * W2[j * OUTD + lane];
    }
    if (lane < OUTD) out[b * OUTD + lane] = o;
}

// ---------------- launch ----------------
extern "C" void kernel_launch(void* const* d_in, const int* in_sizes, int n_in,
                              void* d_out, int out_size)
{
    const float* x     = (const float*)d_in[0];
    const float* W_enc = (const float*)d_in[1];
    const float* b_enc = (const float*)d_in[2];
    const float* theta = (const float*)d_in[3];
    const float* phi   = (const float*)d_in[4];
    const float* W1    = (const float*)d_in[5];
    const float* b1    = (const float*)d_in[6];
    const float* W2    = (const float*)d_in[7];
    const float* b2    = (const float*)d_in[8];
    float* out = (float*)d_out;

    cudaFuncSetAttribute((const void*)pass_kernel,
                         cudaFuncAttributeMaxDynamicSharedMemorySize, 65536);

    prep_kernel<<<256, 256>>>(x, W_enc, b_enc, theta);
    ep_kernel<<<12, 1024>>>(phi);
    dj_kernel<<<1, 64>>>(phi);

    for (int pi = 0; pi < 5; pi++)
        pass_kernel<<<dim3(8, 256), 256, (pi == 4) ? 0 : 65536>>>(pi);

    final_kernel<<<32, 256>>>(W1, b1, W2, b2, out);
}

// round 14
// speedup vs baseline: 1.6334x; 1.1426x over previous
#include <cuda_runtime.h>
#include <math.h>

#define NQ       16
#define BATCH    256
#define NL       4
#define DIN      512
#define OUTD     10

typedef unsigned long long ull;

// ---------------- scratch (SoA state, packed across amp bit 0 = qubit 15) ----------------
__device__ __align__(16) ull g_re[BATCH * 32768];        // 64 MB re pairs
__device__ __align__(16) ull g_im[BATCH * 32768];        // 64 MB im pairs
__device__ float2 g_T1c[BATCH * 256];        // complex product table, amp bits 8..15 (qubits 0..7)
__device__ ull   g_T0Re[BATCH * 128];        // complex product table low (pairs over lane=q15)
__device__ ull   g_T0Im[BATCH * 128];
__device__ ull   g_Rnd[NL * 9 * 12];         // round gates: [l][ubit 0..8] -> qubit 14-ubit
__device__ ull   g_OwnCk[NL * 3 * 12];       // own chunk gates: [pi][kbit]
__device__ ull   g_Def[NL * 3 * 12];         // deferred gates: [slot=layer][kbit]
__device__ ull   g_Lane[NL * 6];             // lane (q15) gate consts
__device__ __align__(16) ull g_EpRe[3 * 4096], g_EpIm[3 * 4096], g_EpImN[3 * 4096];
__device__ ull   g_DjBRe[2*16], g_DjBIm[2*16], g_DjBImN[2*16];  // [l/2][s3][k] layers 0,2
__device__ ull   g_DjARe[32],  g_DjAIm[32],  g_DjAImN[32];      // [k][q2b][t8] layer 1
__device__ float g_zpart[BATCH * 8 * 16];

// ---------------- f32x2 helpers ----------------
__device__ __forceinline__ ull pk2(float lo, float hi) {
    ull r; asm("mov.b64 %0, {%1, %2};" : "=l"(r) : "f"(lo), "f"(hi)); return r;
}
__device__ __forceinline__ ull bc2(float v) {
    ull r; asm("mov.b64 %0, {%1, %1};" : "=l"(r) : "f"(v)); return r;
}
__device__ __forceinline__ void up2(ull v, float& lo, float& hi) {
    asm("mov.b64 {%0, %1}, %2;" : "=f"(lo), "=f"(hi) : "l"(v));
}
__device__ __forceinline__ ull f2fma(ull a, ull b, ull c) {
    ull d; asm("fma.rn.f32x2 %0, %1, %2, %3;" : "=l"(d) : "l"(a), "l"(b), "l"(c)); return d;
}
__device__ __forceinline__ ull f2mul(ull a, ull b) {
    ull d; asm("mul.rn.f32x2 %0, %1, %2;" : "=l"(d) : "l"(a), "l"(b)); return d;
}
__device__ __forceinline__ ull swap2(ull v) {
    float lo, hi; up2(v, lo, hi); return pk2(hi, lo);
}
__device__ __forceinline__ float2 cmulh(float2 a, float2 b) {
    return make_float2(a.x * b.x - a.y * b.y, a.x * b.y + a.y * b.x);
}
__device__ __forceinline__ int swz(int i) { return i ^ (((i >> 3) ^ (i >> 7)) & 15); }

// build layer-l 2x2 gate from theta
__device__ __forceinline__ void build_u(const float* th, float2& u00, float2& u01,
                                        float2& u10, float2& u11)
{
    float a0 = th[0], a1 = th[1], a2 = th[2];
    float ca = cosf(0.5f * a0), sa = sinf(0.5f * a0);
    float cb = cosf(0.5f * a1), sb = sinf(0.5f * a1);
    float cz = cosf(0.5f * a2), sz = sinf(0.5f * a2);
    float2 em = make_float2(cz, -sz);
    float2 ep = make_float2(cz,  sz);
    float2 r00 = make_float2( cb * em.x,  cb * em.y);
    float2 r01 = make_float2(-sb * ep.x, -sb * ep.y);
    float2 r10 = make_float2( sb * em.x,  sb * em.y);
    float2 r11 = make_float2( cb * ep.x,  cb * ep.y);
    u00 = make_float2(ca * r00.x + sa * r10.y, ca * r00.y - sa * r10.x);
    u01 = make_float2(ca * r01.x + sa * r11.y, ca * r01.y - sa * r11.x);
    u10 = make_float2(sa * r00.y + ca * r10.x, -sa * r00.x + ca * r10.y);
    u11 = make_float2(sa * r01.y + ca * r11.x, -sa * r01.x + ca * r11.y);
}

// ---------------- prep ----------------
__global__ void prep_kernel(const float* __restrict__ x,
                            const float* __restrict__ W_enc,
                            const float* __restrict__ b_enc,
                            const float* __restrict__ theta)
{
    __shared__ float partial[256];
    __shared__ float cs[NQ], ss[NQ];
    __shared__ float2 av[16], bv[16];
    __shared__ float2 Ush[NL * NQ * 4];

    int b   = blockIdx.x;
    int tid = threadIdx.x;
    int q   = tid & 15;
    int seg = tid >> 4;

    {
        float acc = 0.f;
        const float* xb = x + b * DIN;
        int d0 = seg * 32;
        #pragma unroll 8
        for (int d = d0; d < d0 + 32; d++)
            acc += xb[d] * W_enc[d * NQ + q];
        partial[tid] = acc;
    }
    __syncthreads();
    if (tid < NQ) {
        float s = b_enc[tid];
        #pragma unroll
        for (int g = 0; g < 16; g++) s += partial[g * 16 + tid];
        float ang = tanhf(s) * 3.14159265358979323846f;
        cs[tid] = cosf(0.5f * ang);
        ss[tid] = sinf(0.5f * ang);
    }
    __syncthreads();

    // fold layer-0 gate into per-qubit vectors: (av,bv) = U_{0,q} . (cos, sin)
    if (tid < NQ) {
        float2 u00, u01, u10, u11;
        build_u(theta + tid * 3, u00, u01, u10, u11);
        float c = cs[tid], s = ss[tid];
        av[tid] = make_float2(u00.x * c + u01.x * s, u00.y * c + u01.y * s);
        bv[tid] = make_float2(u10.x * c + u11.x * s, u10.y * c + u11.y * s);
    }
    __syncthreads();

    // complex product tables
    {   // T1c[m]: amp bits 8..15; m bit j -> qubit 7-j
        int m = tid;
        float2 p = make_float2(1.f, 0.f);
        #pragma unroll
        for (int j = 0; j < 8; j++)
            p = cmulh(p, ((m >> j) & 1) ? bv[7 - j] : av[7 - j]);
        g_T1c[b * 256 + m] = p;
    }
    if (tid < 128) {   // T0 pairs: u bits 0..6 -> qubits 14..8; lane = qubit 15
        int u = tid;
        float2 p = make_float2(1.f, 0.f);
        #pragma unroll
        for (int j = 0; j < 7; j++)
            p = cmulh(p, ((u >> j) & 1) ? bv[14 - j] : av[14 - j]);
        float2 e0 = cmulh(p, av[15]);
        float2 e1 = cmulh(p, bv[15]);
        g_T0Re[b * 128 + u] = pk2(e0.x, e1.x);
        g_T0Im[b * 128 + u] = pk2(e0.y, e1.y);
    }

    if (b == 0) {
        if (tid < NL * NQ) {
            int l = tid >> 4, qq = tid & 15;
            float2 u00, u01, u10, u11;
            build_u(theta + (l * NQ + qq) * 3, u00, u01, u10, u11);
            int base = tid * 4;
            Ush[base + 0] = u00; Ush[base + 1] = u01;
            Ush[base + 2] = u10; Ush[base + 3] = u11;
        }
        __syncthreads();

        // round gates: [l][ubit][12], ubit 0..8 -> qubit 14-ubit
        for (int k = tid; k < NL * 108; k += 256) {
            int l = k / 108, rem = k % 108, ub = rem / 12, e = rem % 12;
            int j2 = e / 3, kind = e % 3;
            float2 u = Ush[(l * 16 + (14 - ub)) * 4 + j2];
            float v = (kind == 0) ? u.x : ((kind == 1) ? u.y : -u.y);
            g_Rnd[k] = bc2(v);
        }
        // own chunk gates: [pi][kbit][12]; covA(pi even): q = 5-kbit; covB: q = 2-kbit
        for (int k = tid; k < NL * 36; k += 256) {
            int pi = k / 36, rem = k % 36, kb = rem / 12, e = rem % 12;
            int qq = ((pi & 1) ? 2 : 5) - kb;
            int j2 = e / 3, kind = e % 3;
            float2 u = Ush[(pi * 16 + qq) * 4 + j2];
            float v = (kind == 0) ? u.x : ((kind == 1) ? u.y : -u.y);
            g_OwnCk[k] = bc2(v);
        }
        // deferred gates: [slot=s][kbit][12]; s even: q = 2-kbit; s odd: q = 5-kbit
        for (int k = tid; k < NL * 36; k += 256) {
            int s = k / 36, rem = k % 36, kb = rem / 12, e = rem % 12;
            int qq = ((s & 1) ? 5 : 2) - kb;
            int j2 = e / 3, kind = e % 3;
            float2 u = Ush[(s * 16 + qq) * 4 + j2];
            float v = (kind == 0) ? u.x : ((kind == 1) ? u.y : -u.y);
            g_Def[k] = bc2(v);
        }
        // lane gate (qubit 15)
        if (tid < NL) {
            int l = tid;
            float2 u00 = Ush[(l * 16 + 15) * 4 + 0];
            float2 u01 = Ush[(l * 16 + 15) * 4 + 1];
            float2 u10 = Ush[(l * 16 + 15) * 4 + 2];
            float2 u11 = Ush[(l * 16 + 15) * 4 + 3];
            g_Lane[l * 6 + 0] = pk2(u00.x, u11.x);
            g_Lane[l * 6 + 1] = pk2(u01.x, u10.x);
            g_Lane[l * 6 + 2] = pk2(-u00.y, -u11.y);
            g_Lane[l * 6 + 3] = pk2(-u01.y, -u10.y);
            g_Lane[l * 6 + 4] = pk2(u00.y, u11.y);
            g_Lane[l * 6 + 5] = pk2(u01.y, u10.y);
        }
    }
}

// ---------------- Ep tables: per-pass epilogue diagonal (passes 0,1,2) ----------------
__global__ void ep_kernel(const float* __restrict__ phi)
{
    int gid = blockIdx.x * 1024 + threadIdx.x;   // 3*4096
    int pi = gid >> 12, u = gid & 4095;
    float ang = 0.f, lp;
    if (pi == 1) {
        #pragma unroll
        for (int bb = 0; bb < 8; bb++) {
            float sA = 1.f - 2.f * ((u >> (bb + 1)) & 1);
            float sB = 1.f - 2.f * ((u >> bb) & 1);
            ang += __ldg(&phi[16 + 13 - bb]) * sA * sB;
        }
        float sq0 = 1.f - 2.f * ((u >> 11) & 1);
        float sq1 = 1.f - 2.f * ((u >> 10) & 1);
        float sq2 = 1.f - 2.f * ((u >> 9) & 1);
        ang += __ldg(&phi[16 + 0]) * sq0 * sq1 + __ldg(&phi[16 + 1]) * sq1 * sq2;
        lp = __ldg(&phi[16 + 14]) * (1.f - 2.f * (u & 1)) + __ldg(&phi[16 + 15]) * sq0;
    } else {
        int l = pi;
        #pragma unroll
        for (int bb = 0; bb < 11; bb++) {
            float sA = 1.f - 2.f * ((u >> (bb + 1)) & 1);
            float sB = 1.f - 2.f * ((u >> bb) & 1);
            ang += __ldg(&phi[l * 16 + 13 - bb]) * sA * sB;
        }
        lp = __ldg(&phi[l * 16 + 14]) * (1.f - 2.f * (u & 1));
    }
    float a0 = ang + lp, a1 = ang - lp;
    float c0, s0, c1, s1;
    sincosf(0.5f * a0, &s0, &c0);
    sincosf(0.5f * a1, &s1, &c1);
    g_EpRe[gid]  = pk2(c0, c1);
    g_EpIm[gid]  = pk2(-s0, -s1);
    g_EpImN[gid] = pk2(s0, s1);
}

// ---------------- Dj tables ----------------
__global__ void dj_kernel(const float* __restrict__ phi)
{
    int tid = threadIdx.x;   // 64
    if (tid < 32) {
        int i = tid;
        int lh = i >> 4, l = lh * 2, s3i = (i >> 3) & 1, k = i & 7;
        float s0v = 1.f - 2.f * ((k >> 2) & 1);
        float s1v = 1.f - 2.f * ((k >> 1) & 1);
        float s2v = 1.f - 2.f * (k & 1);
        float s3v = 1.f - 2.f * (float)s3i;
        const float* ph = phi + l * 16;
        float ang = __ldg(&ph[0]) * s0v * s1v + __ldg(&ph[1]) * s1v * s2v + __ldg(&ph[2]) * s2v * s3v;
        float C = __ldg(&ph[15]) * s0v;
        float a0 = ang + C, a1 = ang - C;
        float c0, s0, c1, s1;
        sincosf(0.5f * a0, &s0, &c0);
        sincosf(0.5f * a1, &s1, &c1);
        g_DjBRe[i]  = pk2(c0, c1);
        g_DjBIm[i]  = pk2(-s0, -s1);
        g_DjBImN[i] = pk2(s0, s1);
    } else {
        int i = tid - 32;
        int k = i >> 2, q2b = (i >> 1) & 1, t8 = i & 1;
        float s3v = 1.f - 2.f * ((k >> 2) & 1);
        float s4v = 1.f - 2.f * ((k >> 1) & 1);
        float s5v = 1.f - 2.f * (k & 1);
        float s2v = 1.f - 2.f * (float)q2b;
        float s6v = 1.f - 2.f * (float)t8;
        const float* ph = phi + 16;
        float ang = __ldg(&ph[2]) * s2v * s3v + __ldg(&ph[3]) * s3v * s4v
                  + __ldg(&ph[4]) * s4v * s5v + __ldg(&ph[5]) * s5v * s6v;
        float c0, s0;
        sincosf(0.5f * ang, &s0, &c0);
        g_DjARe[i]  = bc2(c0);
        g_DjAIm[i]  = bc2(-s0);
        g_DjAImN[i] = bc2(s0);
    }
}

// ---------------- init pass: product state (layer-0 gates folded) + Ep0 diag ----------------
extern "C" __global__ void __launch_bounds__(256)
init_kernel()
{
    const int t    = threadIdx.x;
    const int tile = blockIdx.x;
    const int b    = blockIdx.y;
    const int base = b * 32768 + (tile << 12);

    ull R0 = g_T0Re[b * 128 + (t & 127)];
    ull I0 = g_T0Im[b * 128 + (t & 127)];
    const ull* ER = g_EpRe;     // pi = 0
    const ull* EI = g_EpIm;
    const ull* EN = g_EpImN;

    #pragma unroll
    for (int m = 0; m < 16; m++) {
        int p = (tile << 12) | (m << 8) | t;
        float2 t1 = g_T1c[b * 256 + (p >> 7)];
        ull X = bc2(t1.x), Y = bc2(t1.y), NY = bc2(-t1.y);
        ull re = f2fma(X, R0, f2mul(NY, I0));
        ull im = f2fma(X, I0, f2mul(Y,  R0));
        int u = (m << 8) | t;
        ull cr = __ldg(&ER[u]), ci = __ldg(&EI[u]), cin = __ldg(&EN[u]);
        ull nre = f2fma(cr, re, f2mul(cin, im));
        ull nim = f2fma(cr, im, f2mul(ci,  re));
        g_re[base + u] = nre;
        g_im[base + u] = nim;
    }
}

// ---------------- packed 2x2 gate on 16-value register subcube ----------------
template<int VB>
__device__ __forceinline__ void gate16(ull* ar, ull* ai, const ull* u)
{
    ull u00x = u[0], u00y = u[1],  u00yn = u[2];
    ull u01x = u[3], u01y = u[4],  u01yn = u[5];
    ull u10x = u[6], u10y = u[7],  u10yn = u[8];
    ull u11x = u[9], u11y = u[10], u11yn = u[11];
    #pragma unroll
    for (int m = 0; m < 16; m++) {
        if (m & (1 << VB)) continue;
        int m1 = m | (1 << VB);
        ull axr = ar[m],  axi = ai[m];
        ull bxr = ar[m1], bxi = ai[m1];
        ar[m]  = f2fma(u00x, axr, f2fma(u00yn, axi, f2fma(u01x, bxr, f2mul(u01yn, bxi))));
        ai[m]  = f2fma(u00x, axi, f2fma(u00y,  axr, f2fma(u01x, bxi, f2mul(u01y,  bxr))));
        ar[m1] = f2fma(u10x, axr, f2fma(u10yn, axi, f2fma(u11x, bxr, f2mul(u11yn, bxi))));
        ai[m1] = f2fma(u10x, axi, f2fma(u10y,  axr, f2fma(u11x, bxi, f2mul(u11y,  bxr))));
    }
}

// ---------------- unified pass kernel (pi = 1..4); 256 thr x 16 elems ----------------
extern "C" __global__ void __launch_bounds__(256, 2)
pass_kernel(int pi)
{
    extern __shared__ ull smem[];           // 4096 + 4096 (passes 1..3)
    ull* sre = smem;
    ull* sim = smem + 4096;
    __shared__ ull sR[108];
    __shared__ ull sCk[36], sDf[36], sLn[6];
    __shared__ ull sDjR[16], sDjI[16], sDjN[16];
    __shared__ float wsum[8][16];

    const int t    = threadIdx.x;           // 0..255
    const int tile = blockIdx.x;            // 3 block bits
    const int b    = blockIdx.y;
    const bool covB = (pi == 1 || pi == 3);
    const bool fin  = (pi == 4);
    const int base = b * 32768 + (covB ? (tile << 9) : (tile << 12));

    if (!fin) {
        if (t < 108)               sR[t]        = g_Rnd[pi * 108 + t];
        else if (t < 144)          sCk[t - 108] = g_OwnCk[pi * 36 + (t - 108)];
        else if (t < 150)          sLn[t - 144] = g_Lane[pi * 6 + (t - 144)];
    }
    if (pi > 1) {   // deferred gates exist only for layers 1..3 (layer 0 folded into init)
        if (t >= 160 && t < 196) sDf[t - 160] = g_Def[(pi - 1) * 36 + (t - 160)];
    }
    if (pi == 1 || pi == 3) {
        int s3 = (tile >> 2) & 1, lh = (pi - 1) >> 1;
        if (t >= 200 && t < 208) {
            int k = t - 200;
            sDjR[k] = g_DjBRe[lh * 16 + s3 * 8 + k];
            sDjI[k] = g_DjBIm[lh * 16 + s3 * 8 + k];
            sDjN[k] = g_DjBImN[lh * 16 + s3 * 8 + k];
        }
    } else if (pi == 2) {
        int q2b = tile & 1;
        if (t >= 200 && t < 216) {
            int i = t - 200, k = i >> 1, t8 = i & 1;
            int gi = k * 4 + q2b * 2 + t8;
            sDjR[i] = g_DjARe[gi]; sDjI[i] = g_DjAIm[gi]; sDjN[i] = g_DjAImN[gi];
        }
    }
    __syncthreads();

    // ---- chunk phase: m = u bits 8..11 ----
    ull vr[16], vi[16];
    #pragma unroll
    for (int m = 0; m < 16; m++) {
        int off = covB ? (((m >> 1) << 12) | ((m & 1) << 8) | t)
                       : ((m << 8) | t);
        vr[m] = g_re[base + off];
        vi[m] = g_im[base + off];
    }
    // deferred gates (layer pi-1) on m bits 1,2,3 — only for pi >= 2
    if (pi > 1) {
        gate16<1>(vr, vi, &sDf[0]);
        gate16<2>(vr, vi, &sDf[12]);
        gate16<3>(vr, vi, &sDf[24]);
    }
    // deferred diagonal
    if (pi == 1 || pi == 3) {
        #pragma unroll
        for (int m = 0; m < 16; m++) {
            int k = m >> 1;
            ull cr = sDjR[k], ci = sDjI[k], cin = sDjN[k];
            ull nr = f2fma(cr, vr[m], f2mul(cin, vi[m]));
            vi[m]  = f2fma(cr, vi[m], f2mul(ci,  vr[m]));
            vr[m]  = nr;
        }
    } else if (pi == 2) {
        #pragma unroll
        for (int m = 0; m < 16; m++) {
            ull cr = sDjR[m], ci = sDjI[m], cin = sDjN[m];
            ull nr = f2fma(cr, vr[m], f2mul(cin, vi[m]));
            vi[m]  = f2fma(cr, vi[m], f2mul(ci,  vr[m]));
            vr[m]  = nr;
        }
    }

    if (fin) {
        // ---- expectations ----
        float ptl0 = 0.f, ptl1 = 0.f, a3 = 0.f, a4 = 0.f, a5 = 0.f, a6 = 0.f;
        #pragma unroll
        for (int m = 0; m < 16; m++) {
            ull pp = f2fma(vr[m], vr[m], f2mul(vi[m], vi[m]));
            float l0, l1; up2(pp, l0, l1);
            float pj = l0 + l1;
            ptl0 += l0; ptl1 += l1;
            a3 += ((m >> 3) & 1) ? -pj : pj;
            a4 += ((m >> 2) & 1) ? -pj : pj;
            a5 += ((m >> 1) & 1) ? -pj : pj;
            a6 += ( m       & 1) ? -pj : pj;
        }
        float pt = ptl0 + ptl1;
        float acc[16];
        acc[0] = ((tile >> 2) & 1) ? -pt : pt;
        acc[1] = ((tile >> 1) & 1) ? -pt : pt;
        acc[2] = ( tile       & 1) ? -pt : pt;
        acc[3] = a3; acc[4] = a4; acc[5] = a5; acc[6] = a6;
        #pragma unroll
        for (int q = 7; q < 15; q++)
            acc[q] = ((t >> (14 - q)) & 1) ? -pt : pt;
        acc[15] = ptl0 - ptl1;

        #pragma unroll
        for (int q = 0; q < 16; q++) {
            float v = acc[q];
            #pragma unroll
            for (int o = 16; o > 0; o >>= 1)
                v += __shfl_down_sync(0xffffffffu, v, o);
            if ((t & 31) == 0) wsum[t >> 5][q] = v;
        }
        __syncthreads();
        if (t < 16) {
            float v = 0.f;
            #pragma unroll
            for (int w = 0; w < 8; w++) v += wsum[w][t];
            g_zpart[(b * 8 + tile) * 16 + t] = v;
        }
        return;
    }

    // ---- own layer in chunk phase: lane + chunk gates + q6 ----
    {
        ull P1 = sLn[0], P2 = sLn[1], P3 = sLn[2], P4 = sLn[3], P5 = sLn[4], P6 = sLn[5];
        #pragma unroll
        for (int m = 0; m < 16; m++) {
            ull sar = swap2(vr[m]), sai = swap2(vi[m]);
            ull nr = f2fma(P1, vr[m], f2fma(P2, sar, f2fma(P3, vi[m], f2mul(P4, sai))));
            ull ni = f2fma(P1, vi[m], f2fma(P2, sai, f2fma(P5, vr[m], f2mul(P6, sar))));
            vr[m] = nr; vi[m] = ni;
        }
    }
    gate16<1>(vr, vi, &sCk[0]);
    gate16<2>(vr, vi, &sCk[12]);
    gate16<3>(vr, vi, &sCk[24]);
    gate16<0>(vr, vi, &sR[96]);        // q6 (u bit 8)

    #pragma unroll
    for (int m = 0; m < 16; m++) {
        int s = swz((m << 8) | t);
        sre[s] = vr[m];
        sim[s] = vi[m];
    }
    __syncthreads();

    // ---- round 1: m = u bits 0..3 (q14,q13,q12,q11) ----
    {
        ull ar[16], ai[16];
        #pragma unroll
        for (int m = 0; m < 16; m++) {
            int s = swz((t << 4) | m);
            ar[m] = sre[s]; ai[m] = sim[s];
        }
        gate16<0>(ar, ai, &sR[0]);
        gate16<1>(ar, ai, &sR[12]);
        gate16<2>(ar, ai, &sR[24]);
        gate16<3>(ar, ai, &sR[36]);
        #pragma unroll
        for (int m = 0; m < 16; m++) {
            int s = swz((t << 4) | m);
            sre[s] = ar[m]; sim[s] = ai[m];
        }
    }
    __syncthreads();

    // ---- round 2: m = u bits 4..7 (q10,q9,q8,q7) + Ep diag + global store ----
    {
        ull ar[16], ai[16];
        int hi = t >> 4, lo = t & 15;
        #pragma unroll
        for (int m = 0; m < 16; m++) {
            int s = swz((hi << 8) | (m << 4) | lo);
            ar[m] = sre[s]; ai[m] = sim[s];
        }
        gate16<0>(ar, ai, &sR[48]);
        gate16<1>(ar, ai, &sR[60]);
        gate16<2>(ar, ai, &sR[72]);
        gate16<3>(ar, ai, &sR[84]);

        if (pi < 3) {
            const ull* ER = g_EpRe  + pi * 4096;
            const ull* EI = g_EpIm  + pi * 4096;
            const ull* EN = g_EpImN + pi * 4096;
            #pragma unroll
            for (int m = 0; m < 16; m++) {
                int u = (hi << 8) | (m << 4) | lo;
                ull cr = __ldg(&ER[u]), ci = __ldg(&EI[u]), cin = __ldg(&EN[u]);
                ull nr = f2fma(cr, ar[m], f2mul(cin, ai[m]));
                ai[m]  = f2fma(cr, ai[m], f2mul(ci,  ar[m]));
                ar[m]  = nr;
            }
        }

        #pragma unroll
        for (int m = 0; m < 16; m++) {
            int u = (hi << 8) | (m << 4) | lo;
            int off = covB ? ((u & 511) | ((u >> 9) << 12)) : u;
            g_re[base + off] = ar[m];
            g_im[base + off] = ai[m];
        }
    }
}

// ---------------- final reduce + MLP ----------------
__global__ void final_kernel(const float* __restrict__ W1, const float* __restrict__ b1,
                             const float* __restrict__ W2, const float* __restrict__ b2,
                             float* __restrict__ out)
{
    int t = threadIdx.x;
    int warp = t >> 5, lane = t & 31;
    int b = blockIdx.x * 8 + warp;

    float z = 0.f;
    if (lane < 16) {
        #pragma unroll
        for (int c = 0; c < 8; c++) z += g_zpart[(b * 8 + c) * 16 + lane];
    }
    float h = b1[lane];
    #pragma unroll
    for (int q = 0; q < 16; q++) {
        float zq = __shfl_sync(0xffffffffu, z, q);
        h += zq * W1[q * 32 + lane];
    }
    h = fmaxf(h, 0.f);

    float o = (lane < OUTD) ? b2[lane] : 0.f;
    #pragma unroll
    for (int j = 0; j < 32; j++) {
        float hj = __shfl_sync(0xffffffffu, h, j);
        if (lane < OUTD) o += hj * W2[j * OUTD + lane];
    }
    if (lane < OUTD) out[b * OUTD + lane] = o;
}

// ---------------- launch ----------------
extern "C" void kernel_launch(void* const* d_in, const int* in_sizes, int n_in,
                              void* d_out, int out_size)
{
    const float* x     = (const float*)d_in[0];
    const float* W_enc = (const float*)d_in[1];
    const float* b_enc = (const float*)d_in[2];
    const float* theta = (const float*)d_in[3];
    const float* phi   = (const float*)d_in[4];
    const float* W1    = (const float*)d_in[5];
    const float* b1    = (const float*)d_in[6];
    const float* W2    = (const float*)d_in[7];
    const float* b2    = (const float*)d_in[8];
    float* out = (float*)d_out;

    cudaFuncSetAttribute((const void*)pass_kernel,
                         cudaFuncAttributeMaxDynamicSharedMemorySize, 65536);

    prep_kernel<<<256, 256>>>(x, W_enc, b_enc, theta);
    ep_kernel<<<12, 1024>>>(phi);
    dj_kernel<<<1, 64>>>(phi);

    init_kernel<<<dim3(8, 256), 256>>>();
    for (int pi = 1; pi < 5; pi++)
        pass_kernel<<<dim3(8, 256), 256, (pi == 4) ? 0 : 65536>>>(pi);

    final_kernel<<<32, 256>>>(W1, b1, W2, b2, out);
}

// round 16
// speedup vs baseline: 1.8285x; 1.1195x over previous
#include <cuda_runtime.h>
#include <math.h>

#define NQ       16
#define BATCH    256
#define NL       4
#define DIN      512
#define OUTD     10

typedef unsigned long long ull;

// ---------------- scratch (SoA state, packed across amp bit 0 = qubit 15) ----------------
__device__ __align__(16) ull g_re[BATCH * 32768];        // 64 MB re pairs
__device__ __align__(16) ull g_im[BATCH * 32768];        // 64 MB im pairs
__device__ float2 g_T1c[BATCH * 256];        // complex product table, amp bits 8..15 (qubits 0..7)
__device__ ull   g_T0Re[BATCH * 128];        // complex product table low (pairs over lane=q15)
__device__ ull   g_T0Im[BATCH * 128];
__device__ ull   g_Rnd[NL * 9 * 12];         // round gates: [l][ubit 0..8] -> qubit 14-ubit
__device__ ull   g_OwnCk[NL * 3 * 12];       // own chunk gates: [pi][kbit]
__device__ ull   g_Def[NL * 3 * 12];         // deferred gates: [slot=layer][kbit]
__device__ ull   g_Lane[NL * 6];             // lane (q15) gate consts
__device__ __align__(16) ull g_EpRe[3 * 4096], g_EpIm[3 * 4096], g_EpImN[3 * 4096];
__device__ ull   g_DjBRe[2*16], g_DjBIm[2*16], g_DjBImN[2*16];  // [l/2][s3][k] layers 0,2
__device__ ull   g_DjARe[32],  g_DjAIm[32],  g_DjAImN[32];      // [k][q2b][t8] layer 1
__device__ float g_zpart[BATCH * 8 * 16];

// ---------------- f32x2 helpers ----------------
__device__ __forceinline__ ull pk2(float lo, float hi) {
    ull r; asm("mov.b64 %0, {%1, %2};" : "=l"(r) : "f"(lo), "f"(hi)); return r;
}
__device__ __forceinline__ ull bc2(float v) {
    ull r; asm("mov.b64 %0, {%1, %1};" : "=l"(r) : "f"(v)); return r;
}
__device__ __forceinline__ void up2(ull v, float& lo, float& hi) {
    asm("mov.b64 {%0, %1}, %2;" : "=f"(lo), "=f"(hi) : "l"(v));
}
__device__ __forceinline__ ull f2fma(ull a, ull b, ull c) {
    ull d; asm("fma.rn.f32x2 %0, %1, %2, %3;" : "=l"(d) : "l"(a), "l"(b), "l"(c)); return d;
}
__device__ __forceinline__ ull f2mul(ull a, ull b) {
    ull d; asm("mul.rn.f32x2 %0, %1, %2;" : "=l"(d) : "l"(a), "l"(b)); return d;
}
__device__ __forceinline__ ull swap2(ull v) {
    float lo, hi; up2(v, lo, hi); return pk2(hi, lo);
}
__device__ __forceinline__ float2 cmulh(float2 a, float2 b) {
    return make_float2(a.x * b.x - a.y * b.y, a.x * b.y + a.y * b.x);
}
__device__ __forceinline__ int swz(int i) { return i ^ (((i >> 3) ^ (i >> 7)) & 15); }

// build layer-l 2x2 gate from theta
__device__ __forceinline__ void build_u(const float* th, float2& u00, float2& u01,
                                        float2& u10, float2& u11)
{
    float a0 = th[0], a1 = th[1], a2 = th[2];
    float ca = cosf(0.5f * a0), sa = sinf(0.5f * a0);
    float cb = cosf(0.5f * a1), sb = sinf(0.5f * a1);
    float cz = cosf(0.5f * a2), sz = sinf(0.5f * a2);
    float2 em = make_float2(cz, -sz);
    float2 ep = make_float2(cz,  sz);
    float2 r00 = make_float2( cb * em.x,  cb * em.y);
    float2 r01 = make_float2(-sb * ep.x, -sb * ep.y);
    float2 r10 = make_float2( sb * em.x,  sb * em.y);
    float2 r11 = make_float2( cb * ep.x,  cb * ep.y);
    u00 = make_float2(ca * r00.x + sa * r10.y, ca * r00.y - sa * r10.x);
    u01 = make_float2(ca * r01.x + sa * r11.y, ca * r01.y - sa * r11.x);
    u10 = make_float2(sa * r00.y + ca * r10.x, -sa * r00.x + ca * r10.y);
    u11 = make_float2(sa * r01.y + ca * r11.x, -sa * r01.x + ca * r11.y);
}

// ---------------- prep ----------------
__global__ void prep_kernel(const float* __restrict__ x,
                            const float* __restrict__ W_enc,
                            const float* __restrict__ b_enc,
                            const float* __restrict__ theta)
{
    __shared__ float partial[256];
    __shared__ float cs[NQ], ss[NQ];
    __shared__ float2 av[16], bv[16];
    __shared__ float2 Ush[NL * NQ * 4];

    int b   = blockIdx.x;
    int tid = threadIdx.x;
    int q   = tid & 15;
    int seg = tid >> 4;

    {
        float acc = 0.f;
        const float* xb = x + b * DIN;
        int d0 = seg * 32;
        #pragma unroll 8
        for (int d = d0; d < d0 + 32; d++)
            acc += xb[d] * W_enc[d * NQ + q];
        partial[tid] = acc;
    }
    __syncthreads();
    if (tid < NQ) {
        float s = b_enc[tid];
        #pragma unroll
        for (int g = 0; g < 16; g++) s += partial[g * 16 + tid];
        float ang = tanhf(s) * 3.14159265358979323846f;
        cs[tid] = cosf(0.5f * ang);
        ss[tid] = sinf(0.5f * ang);
    }
    __syncthreads();

    // fold layer-0 gate into per-qubit vectors: (av,bv) = U_{0,q} . (cos, sin)
    if (tid < NQ) {
        float2 u00, u01, u10, u11;
        build_u(theta + tid * 3, u00, u01, u10, u11);
        float c = cs[tid], s = ss[tid];
        av[tid] = make_float2(u00.x * c + u01.x * s, u00.y * c + u01.y * s);
        bv[tid] = make_float2(u10.x * c + u11.x * s, u10.y * c + u11.y * s);
    }
    __syncthreads();

    // complex product tables
    {   // T1c[m]: amp bits 8..15; m bit j -> qubit 7-j
        int m = tid;
        float2 p = make_float2(1.f, 0.f);
        #pragma unroll
        for (int j = 0; j < 8; j++)
            p = cmulh(p, ((m >> j) & 1) ? bv[7 - j] : av[7 - j]);
        g_T1c[b * 256 + m] = p;
    }
    if (tid < 128) {   // T0 pairs: u bits 0..6 -> qubits 14..8; lane = qubit 15
        int u = tid;
        float2 p = make_float2(1.f, 0.f);
        #pragma unroll
        for (int j = 0; j < 7; j++)
            p = cmulh(p, ((u >> j) & 1) ? bv[14 - j] : av[14 - j]);
        float2 e0 = cmulh(p, av[15]);
        float2 e1 = cmulh(p, bv[15]);
        g_T0Re[b * 128 + u] = pk2(e0.x, e1.x);
        g_T0Im[b * 128 + u] = pk2(e0.y, e1.y);
    }

    if (b == 0) {
        if (tid < NL * NQ) {
            int l = tid >> 4, qq = tid & 15;
            float2 u00, u01, u10, u11;
            build_u(theta + (l * NQ + qq) * 3, u00, u01, u10, u11);
            int base = tid * 4;
            Ush[base + 0] = u00; Ush[base + 1] = u01;
            Ush[base + 2] = u10; Ush[base + 3] = u11;
        }
        __syncthreads();

        // round gates: [l][ubit][12], ubit 0..8 -> qubit 14-ubit
        for (int k = tid; k < NL * 108; k += 256) {
            int l = k / 108, rem = k % 108, ub = rem / 12, e = rem % 12;
            int j2 = e / 3, kind = e % 3;
            float2 u = Ush[(l * 16 + (14 - ub)) * 4 + j2];
            float v = (kind == 0) ? u.x : ((kind == 1) ? u.y : -u.y);
            g_Rnd[k] = bc2(v);
        }
        // own chunk gates: [pi][kbit][12]; covA(pi even): q = 5-kbit; covB: q = 2-kbit
        for (int k = tid; k < NL * 36; k += 256) {
            int pi = k / 36, rem = k % 36, kb = rem / 12, e = rem % 12;
            int qq = ((pi & 1) ? 2 : 5) - kb;
            int j2 = e / 3, kind = e % 3;
            float2 u = Ush[(pi * 16 + qq) * 4 + j2];
            float v = (kind == 0) ? u.x : ((kind == 1) ? u.y : -u.y);
            g_OwnCk[k] = bc2(v);
        }
        // deferred gates: [slot=s][kbit][12]; s even: q = 2-kbit; s odd: q = 5-kbit
        for (int k = tid; k < NL * 36; k += 256) {
            int s = k / 36, rem = k % 36, kb = rem / 12, e = rem % 12;
            int qq = ((s & 1) ? 5 : 2) - kb;
            int j2 = e / 3, kind = e % 3;
            float2 u = Ush[(s * 16 + qq) * 4 + j2];
            float v = (kind == 0) ? u.x : ((kind == 1) ? u.y : -u.y);
            g_Def[k] = bc2(v);
        }
        // lane gate (qubit 15)
        if (tid < NL) {
            int l = tid;
            float2 u00 = Ush[(l * 16 + 15) * 4 + 0];
            float2 u01 = Ush[(l * 16 + 15) * 4 + 1];
            float2 u10 = Ush[(l * 16 + 15) * 4 + 2];
            float2 u11 = Ush[(l * 16 + 15) * 4 + 3];
            g_Lane[l * 6 + 0] = pk2(u00.x, u11.x);
            g_Lane[l * 6 + 1] = pk2(u01.x, u10.x);
            g_Lane[l * 6 + 2] = pk2(-u00.y, -u11.y);
            g_Lane[l * 6 + 3] = pk2(-u01.y, -u10.y);
            g_Lane[l * 6 + 4] = pk2(u00.y, u11.y);
            g_Lane[l * 6 + 5] = pk2(u01.y, u10.y);
        }
    }
}

// ---------------- Ep tables: per-pass epilogue diagonal (passes 0,1,2) ----------------
__global__ void ep_kernel(const float* __restrict__ phi)
{
    int gid = blockIdx.x * 1024 + threadIdx.x;   // 3*4096
    int pi = gid >> 12, u = gid & 4095;
    float ang = 0.f, lp;
    if (pi == 1) {
        #pragma unroll
        for (int bb = 0; bb < 8; bb++) {
            float sA = 1.f - 2.f * ((u >> (bb + 1)) & 1);
            float sB = 1.f - 2.f * ((u >> bb) & 1);
            ang += __ldg(&phi[16 + 13 - bb]) * sA * sB;
        }
        float sq0 = 1.f - 2.f * ((u >> 11) & 1);
        float sq1 = 1.f - 2.f * ((u >> 10) & 1);
        float sq2 = 1.f - 2.f * ((u >> 9) & 1);
        ang += __ldg(&phi[16 + 0]) * sq0 * sq1 + __ldg(&phi[16 + 1]) * sq1 * sq2;
        lp = __ldg(&phi[16 + 14]) * (1.f - 2.f * (u & 1)) + __ldg(&phi[16 + 15]) * sq0;
    } else {
        int l = pi;
        #pragma unroll
        for (int bb = 0; bb < 11; bb++) {
            float sA = 1.f - 2.f * ((u >> (bb + 1)) & 1);
            float sB = 1.f - 2.f * ((u >> bb) & 1);
            ang += __ldg(&phi[l * 16 + 13 - bb]) * sA * sB;
        }
        lp = __ldg(&phi[l * 16 + 14]) * (1.f - 2.f * (u & 1));
    }
    float a0 = ang + lp, a1 = ang - lp;
    float c0, s0, c1, s1;
    sincosf(0.5f * a0, &s0, &c0);
    sincosf(0.5f * a1, &s1, &c1);
    g_EpRe[gid]  = pk2(c0, c1);
    g_EpIm[gid]  = pk2(-s0, -s1);
    g_EpImN[gid] = pk2(s0, s1);
}

// ---------------- Dj tables ----------------
__global__ void dj_kernel(const float* __restrict__ phi)
{
    int tid = threadIdx.x;   // 64
    if (tid < 32) {
        int i = tid;
        int lh = i >> 4, l = lh * 2, s3i = (i >> 3) & 1, k = i & 7;
        float s0v = 1.f - 2.f * ((k >> 2) & 1);
        float s1v = 1.f - 2.f * ((k >> 1) & 1);
        float s2v = 1.f - 2.f * (k & 1);
        float s3v = 1.f - 2.f * (float)s3i;
        const float* ph = phi + l * 16;
        float ang = __ldg(&ph[0]) * s0v * s1v + __ldg(&ph[1]) * s1v * s2v + __ldg(&ph[2]) * s2v * s3v;
        float C = __ldg(&ph[15]) * s0v;
        float a0 = ang + C, a1 = ang - C;
        float c0, s0, c1, s1;
        sincosf(0.5f * a0, &s0, &c0);
        sincosf(0.5f * a1, &s1, &c1);
        g_DjBRe[i]  = pk2(c0, c1);
        g_DjBIm[i]  = pk2(-s0, -s1);
        g_DjBImN[i] = pk2(s0, s1);
    } else {
        int i = tid - 32;
        int k = i >> 2, q2b = (i >> 1) & 1, t8 = i & 1;
        float s3v = 1.f - 2.f * ((k >> 2) & 1);
        float s4v = 1.f - 2.f * ((k >> 1) & 1);
        float s5v = 1.f - 2.f * (k & 1);
        float s2v = 1.f - 2.f * (float)q2b;
        float s6v = 1.f - 2.f * (float)t8;
        const float* ph = phi + 16;
        float ang = __ldg(&ph[2]) * s2v * s3v + __ldg(&ph[3]) * s3v * s4v
                  + __ldg(&ph[4]) * s4v * s5v + __ldg(&ph[5]) * s5v * s6v;
        float c0, s0;
        sincosf(0.5f * ang, &s0, &c0);
        g_DjARe[i]  = bc2(c0);
        g_DjAIm[i]  = bc2(-s0);
        g_DjAImN[i] = bc2(s0);
    }
}

// ---------------- packed 2x2 gate on 16-value register subcube ----------------
template<int VB>
__device__ __forceinline__ void gate16(ull* ar, ull* ai, const ull* u)
{
    ull u00x = u[0], u00y = u[1],  u00yn = u[2];
    ull u01x = u[3], u01y = u[4],  u01yn = u[5];
    ull u10x = u[6], u10y = u[7],  u10yn = u[8];
    ull u11x = u[9], u11y = u[10], u11yn = u[11];
    #pragma unroll
    for (int m = 0; m < 16; m++) {
        if (m & (1 << VB)) continue;
        int m1 = m | (1 << VB);
        ull axr = ar[m],  axi = ai[m];
        ull bxr = ar[m1], bxi = ai[m1];
        ar[m]  = f2fma(u00x, axr, f2fma(u00yn, axi, f2fma(u01x, bxr, f2mul(u01yn, bxi))));
        ai[m]  = f2fma(u00x, axi, f2fma(u00y,  axr, f2fma(u01x, bxi, f2mul(u01y,  bxr))));
        ar[m1] = f2fma(u10x, axr, f2fma(u10yn, axi, f2fma(u11x, bxr, f2mul(u11yn, bxi))));
        ai[m1] = f2fma(u10x, axi, f2fma(u10y,  axr, f2fma(u11x, bxi, f2mul(u11y,  bxr))));
    }
}

// ---------------- unified pass kernel (pi = 1..4); 256 thr x 16 elems ----------------
// pi==1 generates the state from product tables (init fused) instead of loading it.
extern "C" __global__ void __launch_bounds__(256, 2)
pass_kernel(int pi)
{
    extern __shared__ ull smem[];           // 4096 + 4096 (passes 1..3)
    ull* sre = smem;
    ull* sim = smem + 4096;
    __shared__ ull sR[108];
    __shared__ ull sCk[36], sDf[36], sLn[6];
    __shared__ ull sDjR[16], sDjI[16], sDjN[16];
    __shared__ float wsum[8][16];

    const int t    = threadIdx.x;           // 0..255
    const int tile = blockIdx.x;            // 3 block bits
    const int b    = blockIdx.y;
    const bool covB = (pi == 1 || pi == 3);
    const bool fin  = (pi == 4);
    const int base = b * 32768 + (covB ? (tile << 9) : (tile << 12));

    if (!fin) {
        if (t < 108)               sR[t]        = g_Rnd[pi * 108 + t];
        else if (t < 144)          sCk[t - 108] = g_OwnCk[pi * 36 + (t - 108)];
        else if (t < 150)          sLn[t - 144] = g_Lane[pi * 6 + (t - 144)];
    }
    if (pi > 1) {   // deferred gates exist only for layers 1..3 (layer 0 folded into tables)
        if (t >= 160 && t < 196) sDf[t - 160] = g_Def[(pi - 1) * 36 + (t - 160)];
    }
    if (pi == 1 || pi == 3) {
        int s3 = (tile >> 2) & 1, lh = (pi - 1) >> 1;
        if (t >= 200 && t < 208) {
            int k = t - 200;
            sDjR[k] = g_DjBRe[lh * 16 + s3 * 8 + k];
            sDjI[k] = g_DjBIm[lh * 16 + s3 * 8 + k];
            sDjN[k] = g_DjBImN[lh * 16 + s3 * 8 + k];
        }
    } else if (pi == 2) {
        int q2b = tile & 1;
        if (t >= 200 && t < 216) {
            int i = t - 200, k = i >> 1, t8 = i & 1;
            int gi = k * 4 + q2b * 2 + t8;
            sDjR[i] = g_DjARe[gi]; sDjI[i] = g_DjAIm[gi]; sDjN[i] = g_DjAImN[gi];
        }
    }
    __syncthreads();

    // ---- chunk phase: m = u bits 8..11 ----
    ull vr[16], vi[16];
    if (pi == 1) {
        // generate product state (layer-0 folded) + Ep0 diag, directly in covB layout
        ull R0 = g_T0Re[b * 128 + (t & 127)];
        ull I0 = g_T0Im[b * 128 + (t & 127)];
        int u0 = (tile << 9) | t;
        ull cr0 = __ldg(&g_EpRe[u0]),       ci0 = __ldg(&g_EpIm[u0]),       cn0 = __ldg(&g_EpImN[u0]);
        ull cr1 = __ldg(&g_EpRe[u0 | 256]), ci1 = __ldg(&g_EpIm[u0 | 256]), cn1 = __ldg(&g_EpImN[u0 | 256]);
        #pragma unroll
        for (int m = 0; m < 16; m++) {
            int ps = ((m >> 1) << 12) | (tile << 9) | ((m & 1) << 8) | t;
            float2 t1 = g_T1c[b * 256 + (ps >> 7)];
            ull X = bc2(t1.x), Y = bc2(t1.y), NY = bc2(-t1.y);
            ull re = f2fma(X, R0, f2mul(NY, I0));
            ull im = f2fma(X, I0, f2mul(Y,  R0));
            ull cr = (m & 1) ? cr1 : cr0;
            ull ci = (m & 1) ? ci1 : ci0;
            ull cn = (m & 1) ? cn1 : cn0;
            vr[m] = f2fma(cr, re, f2mul(cn, im));
            vi[m] = f2fma(cr, im, f2mul(ci, re));
        }
    } else {
        #pragma unroll
        for (int m = 0; m < 16; m++) {
            int off = covB ? (((m >> 1) << 12) | ((m & 1) << 8) | t)
                           : ((m << 8) | t);
            vr[m] = g_re[base + off];
            vi[m] = g_im[base + off];
        }
        // deferred gates (layer pi-1) on m bits 1,2,3
        gate16<1>(vr, vi, &sDf[0]);
        gate16<2>(vr, vi, &sDf[12]);
        gate16<3>(vr, vi, &sDf[24]);
    }
    // deferred diagonal
    if (pi == 1 || pi == 3) {
        #pragma unroll
        for (int m = 0; m < 16; m++) {
            int k = m >> 1;
            ull cr = sDjR[k], ci = sDjI[k], cin = sDjN[k];
            ull nr = f2fma(cr, vr[m], f2mul(cin, vi[m]));
            vi[m]  = f2fma(cr, vi[m], f2mul(ci,  vr[m]));
            vr[m]  = nr;
        }
    } else if (pi == 2) {
        #pragma unroll
        for (int m = 0; m < 16; m++) {
            ull cr = sDjR[m], ci = sDjI[m], cin = sDjN[m];
            ull nr = f2fma(cr, vr[m], f2mul(cin, vi[m]));
            vi[m]  = f2fma(cr, vi[m], f2mul(ci,  vr[m]));
            vr[m]  = nr;
        }
    }

    if (fin) {
        // ---- expectations ----
        float ptl0 = 0.f, ptl1 = 0.f, a3 = 0.f, a4 = 0.f, a5 = 0.f, a6 = 0.f;
        #pragma unroll
        for (int m = 0; m < 16; m++) {
            ull pp = f2fma(vr[m], vr[m], f2mul(vi[m], vi[m]));
            float l0, l1; up2(pp, l0, l1);
            float pj = l0 + l1;
            ptl0 += l0; ptl1 += l1;
            a3 += ((m >> 3) & 1) ? -pj : pj;
            a4 += ((m >> 2) & 1) ? -pj : pj;
            a5 += ((m >> 1) & 1) ? -pj : pj;
            a6 += ( m       & 1) ? -pj : pj;
        }
        float pt = ptl0 + ptl1;
        float acc[16];
        acc[0] = ((tile >> 2) & 1) ? -pt : pt;
        acc[1] = ((tile >> 1) & 1) ? -pt : pt;
        acc[2] = ( tile       & 1) ? -pt : pt;
        acc[3] = a3; acc[4] = a4; acc[5] = a5; acc[6] = a6;
        #pragma unroll
        for (int q = 7; q < 15; q++)
            acc[q] = ((t >> (14 - q)) & 1) ? -pt : pt;
        acc[15] = ptl0 - ptl1;

        #pragma unroll
        for (int q = 0; q < 16; q++) {
            float v = acc[q];
            #pragma unroll
            for (int o = 16; o > 0; o >>= 1)
                v += __shfl_down_sync(0xffffffffu, v, o);
            if ((t & 31) == 0) wsum[t >> 5][q] = v;
        }
        __syncthreads();
        if (t < 16) {
            float v = 0.f;
            #pragma unroll
            for (int w = 0; w < 8; w++) v += wsum[w][t];
            g_zpart[(b * 8 + tile) * 16 + t] = v;
        }
        return;
    }

    // ---- own layer in chunk phase: lane + chunk gates + q6 ----
    {
        ull P1 = sLn[0], P2 = sLn[1], P3 = sLn[2], P4 = sLn[3], P5 = sLn[4], P6 = sLn[5];
        #pragma unroll
        for (int m = 0; m < 16; m++) {
            ull sar = swap2(vr[m]), sai = swap2(vi[m]);
            ull nr = f2fma(P1, vr[m], f2fma(P2, sar, f2fma(P3, vi[m], f2mul(P4, sai))));
            ull ni = f2fma(P1, vi[m], f2fma(P2, sai, f2fma(P5, vr[m], f2mul(P6, sar))));
            vr[m] = nr; vi[m] = ni;
        }
    }
    gate16<1>(vr, vi, &sCk[0]);
    gate16<2>(vr, vi, &sCk[12]);
    gate16<3>(vr, vi, &sCk[24]);
    gate16<0>(vr, vi, &sR[96]);        // q6 (u bit 8)

    #pragma unroll
    for (int m = 0; m < 16; m++) {
        int s = swz((m << 8) | t);
        sre[s] = vr[m];
        sim[s] = vi[m];
    }
    __syncthreads();

    // ---- round 1: m = u bits 0..3 (q14,q13,q12,q11) ----
    {
        ull ar[16], ai[16];
        #pragma unroll
        for (int m = 0; m < 16; m++) {
            int s = swz((t << 4) | m);
            ar[m] = sre[s]; ai[m] = sim[s];
        }
        gate16<0>(ar, ai, &sR[0]);
        gate16<1>(ar, ai, &sR[12]);
        gate16<2>(ar, ai, &sR[24]);
        gate16<3>(ar, ai, &sR[36]);
        #pragma unroll
        for (int m = 0; m < 16; m++) {
            int s = swz((t << 4) | m);
            sre[s] = ar[m]; sim[s] = ai[m];
        }
    }
    __syncthreads();

    // ---- round 2: m = u bits 4..7 (q10,q9,q8,q7) + Ep diag + global store ----
    {
        ull ar[16], ai[16];
        int hi = t >> 4, lo = t & 15;
        #pragma unroll
        for (int m = 0; m < 16; m++) {
            int s = swz((hi << 8) | (m << 4) | lo);
            ar[m] = sre[s]; ai[m] = sim[s];
        }
        gate16<0>(ar, ai, &sR[48]);
        gate16<1>(ar, ai, &sR[60]);
        gate16<2>(ar, ai, &sR[72]);
        gate16<3>(ar, ai, &sR[84]);

        if (pi < 3) {
            const ull* ER = g_EpRe  + pi * 4096;
            const ull* EI = g_EpIm  + pi * 4096;
            const ull* EN = g_EpImN + pi * 4096;
            #pragma unroll
            for (int m = 0; m < 16; m++) {
                int u = (hi << 8) | (m << 4) | lo;
                ull cr = __ldg(&ER[u]), ci = __ldg(&EI[u]), cin = __ldg(&EN[u]);
                ull nr = f2fma(cr, ar[m], f2mul(cin, ai[m]));
                ai[m]  = f2fma(cr, ai[m], f2mul(ci,  ar[m]));
                ar[m]  = nr;
            }
        }

        #pragma unroll
        for (int m = 0; m < 16; m++) {
            int u = (hi << 8) | (m << 4) | lo;
            int off = covB ? ((u & 511) | ((u >> 9) << 12)) : u;
            g_re[base + off] = ar[m];
            g_im[base + off] = ai[m];
        }
    }
}

// ---------------- final reduce + MLP ----------------
__global__ void final_kernel(const float* __restrict__ W1, const float* __restrict__ b1,
                             const float* __restrict__ W2, const float* __restrict__ b2,
                             float* __restrict__ out)
{
    int t = threadIdx.x;
    int warp = t >> 5, lane = t & 31;
    int b = blockIdx.x * 8 + warp;

    float z = 0.f;
    if (lane < 16) {
        #pragma unroll
        for (int c = 0; c < 8; c++) z += g_zpart[(b * 8 + c) * 16 + lane];
    }
    float h = b1[lane];
    #pragma unroll
    for (int q = 0; q < 16; q++) {
        float zq = __shfl_sync(0xffffffffu, z, q);
        h += zq * W1[q * 32 + lane];
    }
    h = fmaxf(h, 0.f);

    float o = (lane < OUTD) ? b2[lane] : 0.f;
    #pragma unroll
    for (int j = 0; j < 32; j++) {
        float hj = __shfl_sync(0xffffffffu, h, j);
        if (lane < OUTD) o += hj * W2[j * OUTD + lane];
    }
    if (lane < OUTD) out[b * OUTD + lane] = o;
}

// ---------------- launch ----------------
extern "C" void kernel_launch(void* const* d_in, const int* in_sizes, int n_in,
                              void* d_out, int out_size)
{
    const float* x     = (const float*)d_in[0];
    const float* W_enc = (const float*)d_in[1];
    const float* b_enc = (const float*)d_in[2];
    const float* theta = (const float*)d_in[3];
    const float* phi   = (const float*)d_in[4];
    const float* W1    = (const float*)d_in[5];
    const float* b1    = (const float*)d_in[6];
    const float* W2    = (const float*)d_in[7];
    const float* b2    = (const float*)d_in[8];
    float* out = (float*)d_out;

    cudaFuncSetAttribute((const void*)pass_kernel,
                         cudaFuncAttributeMaxDynamicSharedMemorySize, 65536);

    prep_kernel<<<256, 256>>>(x, W_enc, b_enc, theta);
    ep_kernel<<<12, 1024>>>(phi);
    dj_kernel<<<1, 64>>>(phi);

    for (int pi = 1; pi < 5; pi++)
        pass_kernel<<<dim3(8, 256), 256, (pi == 4) ? 0 : 65536>>>(pi);

    final_kernel<<<32, 256>>>(W1, b1, W2, b2, out);
}